// round 8
// baseline (speedup 1.0000x reference)
#include <cuda_runtime.h>
#include <cuda_bf16.h>
#include <math.h>
#include <stdint.h>

constexpr int B = 2, N = 2048, C = 1024, H = 16, D = 64, DFF = 4096;
constexpr int BNR = B * N;   // 4096
constexpr float EPS = 1e-5f;

// ---------------- low-level helpers (family-generic PTX: no tcgen05) -------
__device__ __forceinline__ uint32_t smem_u32(const void* p) {
    uint32_t a;
    asm("{ .reg .u64 t; cvta.to.shared.u64 t, %1; cvt.u32.u64 %0, t; }" : "=r"(a) : "l"(p));
    return a;
}
__device__ __forceinline__ void cpasync16(uint32_t dst, const void* src) {
    asm volatile("cp.async.cg.shared.global [%0], [%1], 16;" :: "r"(dst), "l"(src));
}
__device__ __forceinline__ void cp_commit() {
    asm volatile("cp.async.commit_group;");
}
template<int Nw>
__device__ __forceinline__ void cp_wait() {
    asm volatile("cp.async.wait_group %0;" :: "n"(Nw));
}
__device__ __forceinline__ void ldsm4(uint32_t* r, uint32_t addr) {
    asm volatile("ldmatrix.sync.aligned.m8n8.x4.shared.b16 {%0,%1,%2,%3}, [%4];"
        : "=r"(r[0]), "=r"(r[1]), "=r"(r[2]), "=r"(r[3]) : "r"(addr));
}
__device__ __forceinline__ void mma16816(float* d, const uint32_t* a, const uint32_t* b) {
    asm volatile("mma.sync.aligned.m16n8k16.row.col.f32.bf16.bf16.f32 "
        "{%0,%1,%2,%3}, {%4,%5,%6,%7}, {%8,%9}, {%0,%1,%2,%3};"
        : "+f"(d[0]), "+f"(d[1]), "+f"(d[2]), "+f"(d[3])
        : "r"(a[0]), "r"(a[1]), "r"(a[2]), "r"(a[3]), "r"(b[0]), "r"(b[1]));
}
__device__ __forceinline__ float gelu_exact(float v) {
    return 0.5f * v * (1.0f + erff(v * 0.70710678118654752f));
}
__device__ __forceinline__ void split2store(__nv_bfloat16* hi, __nv_bfloat16* lo,
                                            float v0, float v1) {
    __nv_bfloat16 h0 = __float2bfloat16(v0), h1 = __float2bfloat16(v1);
    __nv_bfloat162 hh(h0, h1);
    __nv_bfloat162 ll(__float2bfloat16(v0 - __bfloat162float(h0)),
                      __float2bfloat16(v1 - __bfloat162float(h1)));
    *reinterpret_cast<__nv_bfloat162*>(hi) = hh;
    *reinterpret_cast<__nv_bfloat162*>(lo) = ll;
}
__device__ __forceinline__ uint2 cvt_hi2(float4 v) {
    __nv_bfloat162 a(__float2bfloat16(v.x), __float2bfloat16(v.y));
    __nv_bfloat162 b(__float2bfloat16(v.z), __float2bfloat16(v.w));
    return make_uint2(*(uint32_t*)&a, *(uint32_t*)&b);
}
__device__ __forceinline__ uint2 cvt_lo2(float4 v, uint2 hi) {
    __nv_bfloat162 ha = *(__nv_bfloat162*)&hi.x, hb = *(__nv_bfloat162*)&hi.y;
    __nv_bfloat162 a(__float2bfloat16(v.x - __bfloat162float(ha.x)),
                     __float2bfloat16(v.y - __bfloat162float(ha.y)));
    __nv_bfloat162 b(__float2bfloat16(v.z - __bfloat162float(hb.x)),
                     __float2bfloat16(v.w - __bfloat162float(hb.y)));
    return make_uint2(*(uint32_t*)&a, *(uint32_t*)&b);
}

// ---------------- scratch ----------------
#define GA __device__ __align__(256)
GA __nv_bfloat16 g_xnh[BNR * C],      g_xnl[BNR * C];
GA __nv_bfloat16 g_qwh[3 * C * C],    g_qwl[3 * C * C];
GA __nv_bfloat16 g_pwh[C * C],        g_pwl[C * C];
GA __nv_bfloat16 g_f1h[DFF * C],      g_f1l[DFF * C];
GA __nv_bfloat16 g_f2h[C * DFF],      g_f2l[C * DFF];
GA __nv_bfloat16 g_qh[BNR * 3 * C],   g_ql[BNR * 3 * C];
GA __nv_bfloat16 g_vth[B * H * D * N], g_vtl[B * H * D * N];
GA __nv_bfloat16 g_aoh[BNR * C],      g_aol[BNR * C];
GA __nv_bfloat16 g_hh[BNR * DFF],     g_hl[BNR * DFF];
GA float g_x1[BNR * C];
GA float2 g_stats[B * H * N];          // per-row (max, 1/sum)

// ---------------- fp32 -> (hi,lo) bf16 split ----------------
__global__ void split_kernel(const float* __restrict__ s, __nv_bfloat16* __restrict__ hi,
                             __nv_bfloat16* __restrict__ lo, int n4) {
    int i = blockIdx.x * 256 + threadIdx.x;
    if (i >= n4) return;
    float4 v = reinterpret_cast<const float4*>(s)[i];
    uint2 h = cvt_hi2(v);
    uint2 l = cvt_lo2(v, h);
    reinterpret_cast<uint2*>(hi)[i] = h;
    reinterpret_cast<uint2*>(lo)[i] = l;
}

// ---------------- LayerNorm -> split ----------------
__global__ void ln_split(const float* __restrict__ x, const float* __restrict__ g,
                         const float* __restrict__ b, __nv_bfloat16* __restrict__ hi,
                         __nv_bfloat16* __restrict__ lo) {
    const int row = blockIdx.x, tid = threadIdx.x;
    const float* xr = x + (size_t)row * C;
    __shared__ float sd[C];
    __shared__ float red[256];
    float ls = 0.f;
    for (int i = tid; i < C; i += 256) { float v = xr[i]; sd[i] = v; ls += v; }
    red[tid] = ls; __syncthreads();
    for (int s = 128; s > 0; s >>= 1) { if (tid < s) red[tid] += red[tid + s]; __syncthreads(); }
    const float mu = red[0] * (1.0f / C); __syncthreads();
    float lv = 0.f;
    for (int i = tid; i < C; i += 256) { float d = sd[i] - mu; lv += d * d; }
    red[tid] = lv; __syncthreads();
    for (int s = 128; s > 0; s >>= 1) { if (tid < s) red[tid] += red[tid + s]; __syncthreads(); }
    const float rstd = rsqrtf(red[0] * (1.0f / C) + EPS);
    for (int i = tid; i < C; i += 256) {
        float v = (sd[i] - mu) * rstd * g[i] + b[i];
        __nv_bfloat16 h = __float2bfloat16(v);
        hi[(size_t)row * C + i] = h;
        lo[(size_t)row * C + i] = __float2bfloat16(v - __bfloat162float(h));
    }
}

// ---------------- V transpose: qkv[.,2C+h*64+d] -> vt[b,h,d,n] ----------------
__global__ void vtrans(const __nv_bfloat16* __restrict__ qh, const __nv_bfloat16* __restrict__ ql,
                       __nv_bfloat16* __restrict__ vh, __nv_bfloat16* __restrict__ vl) {
    const int z = blockIdx.z, b = z >> 4, h = z & 15;
    const int n0 = blockIdx.x * 32, tid = threadIdx.x;
    __shared__ __nv_bfloat16 sh[64][33], sl[64][33];
    for (int i = tid; i < 2048; i += 256) {
        int r = i >> 6, d = i & 63;
        size_t o = (size_t)(b * N + n0 + r) * (3 * C) + 2 * C + h * 64 + d;
        sh[d][r] = qh[o]; sl[d][r] = ql[o];
    }
    __syncthreads();
    for (int i = tid; i < 2048; i += 256) {
        int d = i >> 5, c = i & 31;
        size_t o = (size_t)z * D * N + (size_t)d * N + n0 + c;
        vh[o] = sh[d][c]; vl[o] = sl[d][c];
    }
}

// ===========================================================================
// scores_stats: per-head row strip. CTA = 128 rows x full N cols of one head.
// Q strip (128x64 hi/lo) loaded once; K tiles (128x64 hi/lo) double-buffered.
// Writes RAW masked scores (scaled, masked -> -INF) to attn and per-row
// online-softmax stats (m, 1/s) to g_stats.
// ===========================================================================
constexpr int SS_QT   = 128 * 80;                 // one 128x32 sub-tile
constexpr int SS_SQ   = 0;                        // Q: 4 * QT  (kc,hl)
constexpr int SS_SK   = 4 * SS_QT;                // K: 2 stages * 4 * QT
constexpr int SS_MASK = SS_SK + 8 * SS_QT;        // 2048 ints
constexpr int SS_STAT = SS_MASK + 8192;           // float2[128][2]
constexpr int SS_SMEM = SS_STAT + 2048;           // 133120

__global__ void __launch_bounds__(256, 1) scores_stats(
    const __nv_bfloat16* __restrict__ Qh, const __nv_bfloat16* __restrict__ Ql,
    const int* __restrict__ mask,
    float* __restrict__ attn, float2* __restrict__ statsg) {
    extern __shared__ char smem[];
    const int tid = threadIdx.x, lane = tid & 31, wid = tid >> 5;
    const int wm = wid & 3, wn = wid >> 2;
    const int mt = blockIdx.x, z = blockIdx.y;
    const int bz = z >> 4, hz = z & 15;
    const int m0 = mt * 128;
    const uint32_t sbase = smem_u32(smem);
    int* smask = (int*)(smem + SS_MASK);
    float2* sstat = (float2*)(smem + SS_STAT);

    // Q load (both 32-col chunks, hi/lo) + mask
    #pragma unroll
    for (int kc = 0; kc < 2; kc++) {
        #pragma unroll
        for (int i = tid; i < 512; i += 256) {
            int r = i >> 2, c4 = i & 3;
            size_t src = (size_t)(bz * N + m0 + r) * (3 * C) + hz * 64 + kc * 32 + c4 * 8;
            uint32_t d = sbase + SS_SQ + (kc * 2) * SS_QT + r * 80 + c4 * 16;
            cpasync16(d,         Qh + src);
            cpasync16(d + SS_QT, Ql + src);
        }
    }
    for (int i = tid; i < 2048; i += 256) smask[i] = mask[(size_t)bz * N + i];

    auto load_k = [&](int s, int t) {
        #pragma unroll
        for (int kc = 0; kc < 2; kc++) {
            #pragma unroll
            for (int i = tid; i < 512; i += 256) {
                int r = i >> 2, c4 = i & 3;
                size_t src = (size_t)(bz * N + t * 128 + r) * (3 * C) + C + hz * 64 + kc * 32 + c4 * 8;
                uint32_t d = sbase + SS_SK + (s * 4 + kc * 2) * SS_QT + r * 80 + c4 * 16;
                cpasync16(d,         Qh + src);
                cpasync16(d + SS_QT, Ql + src);
            }
        }
        cp_commit();
    };

    load_k(0, 0);    // same group as Q loads

    float m_run[4], s_run[4];
    #pragma unroll
    for (int i = 0; i < 4; i++) { m_run[i] = -INFINITY; s_run[i] = 0.f; }

    const int arow = wm * 32 + (lane & 15);
    const int acolb = ((lane >> 4) << 4);
    const int brow = (lane & 7) + ((lane >> 4) << 3);
    const int bcolb = (((lane >> 3) & 1) << 4);

    for (int t = 0; t < 16; t++) {
        if (t + 1 < 16) { load_k((t + 1) & 1, t + 1); cp_wait<1>(); }
        else cp_wait<0>();
        __syncthreads();

        float acc[2][8][4];
        #pragma unroll
        for (int a = 0; a < 2; a++)
            #pragma unroll
            for (int b2 = 0; b2 < 8; b2++)
                #pragma unroll
                for (int c = 0; c < 4; c++) acc[a][b2][c] = 0.f;

        const uint32_t kst = sbase + SS_SK + (t & 1) * 4 * SS_QT;
        #pragma unroll
        for (int ks = 0; ks < 4; ks++) {
            const int kc = ks >> 1, kk = ks & 1;
            uint32_t afh[2][4], afl[2][4];
            #pragma unroll
            for (int ma = 0; ma < 2; ma++) {
                uint32_t ad = sbase + SS_SQ + (kc * 2) * SS_QT + (arow + ma * 16) * 80 + kk * 32 + acolb;
                ldsm4(afh[ma], ad);
                ldsm4(afl[ma], ad + SS_QT);
            }
            uint32_t bfh[8][2], bfl[8][2];
            #pragma unroll
            for (int p = 0; p < 4; p++) {
                uint32_t r4[4];
                uint32_t bd = kst + (kc * 2) * SS_QT + (wn * 64 + p * 16 + brow) * 80 + kk * 32 + bcolb;
                ldsm4(r4, bd);
                bfh[2*p][0] = r4[0]; bfh[2*p][1] = r4[1];
                bfh[2*p+1][0] = r4[2]; bfh[2*p+1][1] = r4[3];
                ldsm4(r4, bd + SS_QT);
                bfl[2*p][0] = r4[0]; bfl[2*p][1] = r4[1];
                bfl[2*p+1][0] = r4[2]; bfl[2*p+1][1] = r4[3];
            }
            #pragma unroll
            for (int ma = 0; ma < 2; ma++)
                #pragma unroll
                for (int na = 0; na < 8; na++) {
                    mma16816(acc[ma][na], afh[ma], bfh[na]);
                    mma16816(acc[ma][na], afh[ma], bfl[na]);
                    mma16816(acc[ma][na], afl[ma], bfh[na]);
                }
        }
        __syncthreads();

        // epilogue: mask + scale, write raw, online stats
        const int colbase = t * 128 + wn * 64;
        #pragma unroll
        for (int ma = 0; ma < 2; ma++) {
            #pragma unroll
            for (int part = 0; part < 2; part++) {
                const int ridx = ma * 2 + part;
                const int row = m0 + wm * 32 + ma * 16 + part * 8 + (lane >> 2);
                float vmax = -INFINITY;
                #pragma unroll
                for (int na = 0; na < 8; na++) {
                    const int c = colbase + na * 8 + ((lane & 3) << 1);
                    float v0 = smask[c]     ? acc[ma][na][part * 2]     * 0.125f : -INFINITY;
                    float v1 = smask[c + 1] ? acc[ma][na][part * 2 + 1] * 0.125f : -INFINITY;
                    acc[ma][na][part * 2] = v0;
                    acc[ma][na][part * 2 + 1] = v1;
                    *reinterpret_cast<float2*>(attn + (size_t)z * N * N + (size_t)row * N + c)
                        = make_float2(v0, v1);
                    vmax = fmaxf(vmax, fmaxf(v0, v1));
                }
                vmax = fmaxf(vmax, __shfl_xor_sync(0xffffffffu, vmax, 1));
                vmax = fmaxf(vmax, __shfl_xor_sync(0xffffffffu, vmax, 2));
                if (vmax == -INFINITY) continue;
                const float mnew = fmaxf(m_run[ridx], vmax);
                float tsum = 0.f;
                #pragma unroll
                for (int na = 0; na < 8; na++) {
                    tsum += __expf(acc[ma][na][part * 2]     - mnew);
                    tsum += __expf(acc[ma][na][part * 2 + 1] - mnew);
                }
                tsum += __shfl_xor_sync(0xffffffffu, tsum, 1);
                tsum += __shfl_xor_sync(0xffffffffu, tsum, 2);
                s_run[ridx] = s_run[ridx] * __expf(m_run[ridx] - mnew) + tsum;
                m_run[ridx] = mnew;
            }
        }
    }

    // cross-warp (wn) combine and store stats
    __syncthreads();
    if ((lane & 3) == 0) {
        #pragma unroll
        for (int ridx = 0; ridx < 4; ridx++) {
            int rl = wm * 32 + (ridx >> 1) * 16 + (ridx & 1) * 8 + (lane >> 2);
            sstat[rl * 2 + wn] = make_float2(m_run[ridx], s_run[ridx]);
        }
    }
    __syncthreads();
    if (tid < 128) {
        float2 a = sstat[tid * 2 + 0], b2 = sstat[tid * 2 + 1];
        float m = fmaxf(a.x, b2.x);
        float s = a.y * __expf(a.x - m) + b2.y * __expf(b2.x - m);
        statsg[(size_t)z * N + m0 + tid] = make_float2(m, 1.0f / s);
    }
}

// ===========================================================================
// HMMA GEMM (NT), 2-stage cp.async (proven: 81920 B smem).
// EPI: 1 = split -> hi/lo   2 = +bias+resid -> fp32   3 = gelu(+bias) -> hi/lo
// ===========================================================================
template<int BN_, int EPI>
__global__ void __launch_bounds__(256, 1) hgemm(
    const __nv_bfloat16* __restrict__ Ah, const __nv_bfloat16* __restrict__ Al,
    int lda, long long sAb, long long sAh,
    const __nv_bfloat16* __restrict__ Bh, const __nv_bfloat16* __restrict__ Bl,
    int ldb, long long sBb, long long sBh,
    float* __restrict__ Cf, __nv_bfloat16* __restrict__ Chi, __nv_bfloat16* __restrict__ Clo,
    int ldc, long long sCb, long long sCh,
    int K, const float* __restrict__ bias, const float* __restrict__ resid) {
    extern __shared__ char smem[];
    constexpr int ROWB = 80;
    constexpr int ATILE = 128 * ROWB;
    constexpr int STAGE = 2 * ATILE + 2 * BN_ * ROWB;
    constexpr int WTN = BN_ / 2;
    constexpr int NA = WTN / 8;

    const int tid = threadIdx.x, lane = tid & 31, wid = tid >> 5;
    const int wm = wid & 3, wn = wid >> 2;
    const int z = blockIdx.z, bz = z >> 4, hz = z & 15;
    Ah += (size_t)bz * sAb + (size_t)hz * sAh;
    Al += (size_t)bz * sAb + (size_t)hz * sAh;
    Bh += (size_t)bz * sBb + (size_t)hz * sBh;
    Bl += (size_t)bz * sBb + (size_t)hz * sBh;
    const size_t coff = (size_t)bz * sCb + (size_t)hz * sCh;
    const int m0 = blockIdx.y * 128, n0 = blockIdx.x * BN_;
    const uint32_t sbase = smem_u32(smem);

    auto load_stage = [&](int s, int k0) {
        const uint32_t st = sbase + s * STAGE;
        #pragma unroll
        for (int i = tid; i < 512; i += 256) {
            int r = i >> 2, c4 = i & 3;
            uint32_t d = st + r * ROWB + c4 * 16;
            cpasync16(d,         Ah + (size_t)(m0 + r) * lda + k0 + c4 * 8);
            cpasync16(d + ATILE, Al + (size_t)(m0 + r) * lda + k0 + c4 * 8);
        }
        #pragma unroll
        for (int i = tid; i < BN_ * 4; i += 256) {
            int r = i >> 2, c4 = i & 3;
            uint32_t d = st + 2 * ATILE + r * ROWB + c4 * 16;
            cpasync16(d,              Bh + (size_t)(n0 + r) * ldb + k0 + c4 * 8);
            cpasync16(d + BN_ * ROWB, Bl + (size_t)(n0 + r) * ldb + k0 + c4 * 8);
        }
        cp_commit();
    };

    float acc[2][NA][4];
    #pragma unroll
    for (int a = 0; a < 2; a++)
        #pragma unroll
        for (int b2 = 0; b2 < NA; b2++)
            #pragma unroll
            for (int c = 0; c < 4; c++) acc[a][b2][c] = 0.f;

    const int nch = K >> 5;
    load_stage(0, 0);
    for (int ch = 0; ch < nch; ch++) {
        if (ch + 1 < nch) { load_stage((ch + 1) & 1, (ch + 1) << 5); cp_wait<1>(); }
        else cp_wait<0>();
        __syncthreads();

        const uint32_t st  = sbase + (ch & 1) * STAGE;
        const uint32_t bst = st + 2 * ATILE;
        const int arow = wm * 32 + (lane & 15);
        const int acolb = ((lane >> 4) << 4);
        const int brow = (lane & 7) + ((lane >> 4) << 3);
        const int bcolb = (((lane >> 3) & 1) << 4);
        #pragma unroll
        for (int ks = 0; ks < 2; ks++) {
            uint32_t afh[2][4], afl[2][4];
            #pragma unroll
            for (int ma = 0; ma < 2; ma++) {
                uint32_t ad = st + (arow + ma * 16) * ROWB + ks * 32 + acolb;
                ldsm4(afh[ma], ad);
                ldsm4(afl[ma], ad + ATILE);
            }
            uint32_t bfh[NA][2], bfl[NA][2];
            #pragma unroll
            for (int p = 0; p < NA / 2; p++) {
                uint32_t r4[4];
                uint32_t bd = bst + (wn * WTN + p * 16 + brow) * ROWB + ks * 32 + bcolb;
                ldsm4(r4, bd);
                bfh[2*p][0] = r4[0]; bfh[2*p][1] = r4[1];
                bfh[2*p+1][0] = r4[2]; bfh[2*p+1][1] = r4[3];
                ldsm4(r4, bd + BN_ * ROWB);
                bfl[2*p][0] = r4[0]; bfl[2*p][1] = r4[1];
                bfl[2*p+1][0] = r4[2]; bfl[2*p+1][1] = r4[3];
            }
            #pragma unroll
            for (int ma = 0; ma < 2; ma++)
                #pragma unroll
                for (int na = 0; na < NA; na++) {
                    mma16816(acc[ma][na], afh[ma], bfh[na]);
                    mma16816(acc[ma][na], afh[ma], bfl[na]);
                    mma16816(acc[ma][na], afl[ma], bfh[na]);
                }
        }
        __syncthreads();
    }

    #pragma unroll
    for (int ma = 0; ma < 2; ma++)
        #pragma unroll
        for (int na = 0; na < NA; na++) {
            const int gr0 = m0 + wm * 32 + ma * 16 + (lane >> 2);
            const int gc  = n0 + wn * WTN + na * 8 + ((lane & 3) << 1);
            #pragma unroll
            for (int h2 = 0; h2 < 2; h2++) {
                const int gr = gr0 + h2 * 8;
                float v0 = acc[ma][na][h2 * 2], v1 = acc[ma][na][h2 * 2 + 1];
                const size_t o = coff + (size_t)gr * ldc + gc;
                if (EPI == 1) split2store(Chi + o, Clo + o, v0, v1);
                if (EPI == 2) {
                    *reinterpret_cast<float2*>(Cf + o) = make_float2(
                        v0 + bias[gc]     + resid[(size_t)gr * ldc + gc],
                        v1 + bias[gc + 1] + resid[(size_t)gr * ldc + gc + 1]);
                }
                if (EPI == 3) {
                    float t0 = gelu_exact(v0 + bias[gc]);
                    float t1 = gelu_exact(v1 + bias[gc + 1]);
                    split2store(Chi + o, Clo + o, t0, t1);
                }
            }
        }
}

// ===========================================================================
// av_gemm: A = RAW scores fp32 [N,N] per head. Applies softmax normalize
// (exp(v-m)*inv) in registers, writes normalized attn fp32 back IN PLACE,
// converts to bf16 hi/lo for the MMA. B = vt [D,N] hi/lo. 2-stage.
// ===========================================================================
__global__ void __launch_bounds__(256, 1) av_gemm(
    float* __restrict__ attn, const float2* __restrict__ statsg,
    const __nv_bfloat16* __restrict__ Vh, const __nv_bfloat16* __restrict__ Vl,
    __nv_bfloat16* __restrict__ Ohi, __nv_bfloat16* __restrict__ Olo) {
    extern __shared__ char smem[];
    constexpr int ROWB = 80;
    constexpr int ATILE = 128 * ROWB;
    constexpr int BTILE = 64 * ROWB;
    constexpr int STAGE = 2 * ATILE + 2 * BTILE;
    constexpr int NA = 4;

    const int tid = threadIdx.x, lane = tid & 31, wid = tid >> 5;
    const int wm = wid & 3, wn = wid >> 2;
    const int z = blockIdx.z, bz = z >> 4, hz = z & 15;
    const int m0 = blockIdx.x * 128;
    float* Ab = attn + (size_t)z * N * N;
    const __nv_bfloat16* Bh = Vh + (size_t)z * D * N;
    const __nv_bfloat16* Bl = Vl + (size_t)z * D * N;
    const uint32_t sbase = smem_u32(smem);

    float4 areg[4];
    auto ldg_A = [&](int k0) {
        #pragma unroll
        for (int j = 0; j < 4; j++) {
            int i = tid + j * 256;
            int r = i >> 3, c4 = i & 7;
            areg[j] = *reinterpret_cast<const float4*>(Ab + (size_t)(m0 + r) * N + k0 + c4 * 4);
        }
    };
    // normalize + write back + stage hi/lo into smem
    auto sts_A = [&](int s, int k0) {
        #pragma unroll
        for (int j = 0; j < 4; j++) {
            int i = tid + j * 256;
            int r = i >> 3, c4 = i & 7;
            float2 st = statsg[(size_t)z * N + m0 + r];
            float4 v = areg[j];
            float4 p;
            p.x = __expf(v.x - st.x) * st.y;
            p.y = __expf(v.y - st.x) * st.y;
            p.z = __expf(v.z - st.x) * st.y;
            p.w = __expf(v.w - st.x) * st.y;
            *reinterpret_cast<float4*>(Ab + (size_t)(m0 + r) * N + k0 + c4 * 4) = p;
            uint2 h = cvt_hi2(p);
            uint2 l = cvt_lo2(p, h);
            *reinterpret_cast<uint2*>(smem + s * STAGE + r * ROWB + c4 * 8) = h;
            *reinterpret_cast<uint2*>(smem + s * STAGE + ATILE + r * ROWB + c4 * 8) = l;
        }
    };
    auto ld_B = [&](int s, int k0) {
        const uint32_t st = sbase + s * STAGE + 2 * ATILE;
        {
            int i = tid;
            int r = i >> 2, c4 = i & 3;
            uint32_t d = st + r * ROWB + c4 * 16;
            cpasync16(d,         Bh + (size_t)r * N + k0 + c4 * 8);
            cpasync16(d + BTILE, Bl + (size_t)r * N + k0 + c4 * 8);
        }
        cp_commit();
    };

    float acc[2][NA][4];
    #pragma unroll
    for (int a = 0; a < 2; a++)
        #pragma unroll
        for (int b2 = 0; b2 < NA; b2++)
            #pragma unroll
            for (int c = 0; c < 4; c++) acc[a][b2][c] = 0.f;

    constexpr int nch = N / 32;    // 64
    ldg_A(0);
    sts_A(0, 0);
    ld_B(0, 0);
    ldg_A(32);

    for (int ch = 0; ch < nch; ch++) {
        if (ch + 1 < nch) {
            sts_A((ch + 1) & 1, (ch + 1) << 5);
            ld_B((ch + 1) & 1, (ch + 1) << 5);
        }
        if (ch + 2 < nch) ldg_A((ch + 2) << 5);
        if (ch + 1 < nch) cp_wait<1>(); else cp_wait<0>();
        __syncthreads();

        const uint32_t st  = sbase + (ch & 1) * STAGE;
        const uint32_t bst = st + 2 * ATILE;
        const int arow = wm * 32 + (lane & 15);
        const int acolb = ((lane >> 4) << 4);
        const int brow = (lane & 7) + ((lane >> 4) << 3);
        const int bcolb = (((lane >> 3) & 1) << 4);
        #pragma unroll
        for (int ks = 0; ks < 2; ks++) {
            uint32_t afh[2][4], afl[2][4];
            #pragma unroll
            for (int ma = 0; ma < 2; ma++) {
                uint32_t ad = st + (arow + ma * 16) * ROWB + ks * 32 + acolb;
                ldsm4(afh[ma], ad);
                ldsm4(afl[ma], ad + ATILE);
            }
            uint32_t bfh[NA][2], bfl[NA][2];
            #pragma unroll
            for (int p = 0; p < NA / 2; p++) {
                uint32_t r4[4];
                uint32_t bd = bst + (wn * 32 + p * 16 + brow) * ROWB + ks * 32 + bcolb;
                ldsm4(r4, bd);
                bfh[2*p][0] = r4[0]; bfh[2*p][1] = r4[1];
                bfh[2*p+1][0] = r4[2]; bfh[2*p+1][1] = r4[3];
                ldsm4(r4, bd + BTILE);
                bfl[2*p][0] = r4[0]; bfl[2*p][1] = r4[1];
                bfl[2*p+1][0] = r4[2]; bfl[2*p+1][1] = r4[3];
            }
            #pragma unroll
            for (int ma = 0; ma < 2; ma++)
                #pragma unroll
                for (int na = 0; na < NA; na++) {
                    mma16816(acc[ma][na], afh[ma], bfh[na]);
                    mma16816(acc[ma][na], afh[ma], bfl[na]);
                    mma16816(acc[ma][na], afl[ma], bfh[na]);
                }
        }
        __syncthreads();
    }

    #pragma unroll
    for (int ma = 0; ma < 2; ma++)
        #pragma unroll
        for (int na = 0; na < NA; na++) {
            const int lr0 = wm * 32 + ma * 16 + (lane >> 2);
            const int gc  = hz * 64 + wn * 32 + na * 8 + ((lane & 3) << 1);
            #pragma unroll
            for (int h2 = 0; h2 < 2; h2++) {
                const size_t o = (size_t)(bz * N + m0 + lr0 + h2 * 8) * C + gc;
                split2store(Ohi + o, Olo + o, acc[ma][na][h2 * 2], acc[ma][na][h2 * 2 + 1]);
            }
        }
}

constexpr int SMB128 = 2 * (2 * 128 * 80 + 2 * 128 * 80);  // 81920
constexpr int SMB_AV = 2 * (2 * 128 * 80 + 2 * 64 * 80);   // 61440

// ---------------- host ----------------
extern "C" void kernel_launch(void* const* d_in, const int* in_sizes, int n_in,
                              void* d_out, int out_size) {
    const float* x      = (const float*)d_in[0];
    const int*   mask   = (const int*)  d_in[1];
    const float* qkv_w  = (const float*)d_in[2];
    const float* proj_w = (const float*)d_in[3];
    const float* proj_b = (const float*)d_in[4];
    const float* ln1_g  = (const float*)d_in[5];
    const float* ln1_b  = (const float*)d_in[6];
    const float* ln2_g  = (const float*)d_in[7];
    const float* ln2_b  = (const float*)d_in[8];
    const float* fc1_w  = (const float*)d_in[9];
    const float* fc1_b  = (const float*)d_in[10];
    const float* fc2_w  = (const float*)d_in[11];
    const float* fc2_b  = (const float*)d_in[12];
    float* out_x    = (float*)d_out;
    float* out_attn = out_x + (size_t)B * N * C;

    cudaFuncSetAttribute(hgemm<128,1>, cudaFuncAttributeMaxDynamicSharedMemorySize, SMB128);
    cudaFuncSetAttribute(hgemm<128,2>, cudaFuncAttributeMaxDynamicSharedMemorySize, SMB128);
    cudaFuncSetAttribute(hgemm<128,3>, cudaFuncAttributeMaxDynamicSharedMemorySize, SMB128);
    cudaFuncSetAttribute(av_gemm,      cudaFuncAttributeMaxDynamicSharedMemorySize, SMB_AV);
    cudaFuncSetAttribute(scores_stats, cudaFuncAttributeMaxDynamicSharedMemorySize, SS_SMEM);

    __nv_bfloat16 *xnh, *xnl, *qwh, *qwl, *pwh, *pwl, *f1h, *f1l, *f2h, *f2l;
    __nv_bfloat16 *qh, *ql, *vth, *vtl, *aoh, *aol, *hh, *hl;
    float* x1;
    float2* stats;
    cudaGetSymbolAddress((void**)&xnh, g_xnh); cudaGetSymbolAddress((void**)&xnl, g_xnl);
    cudaGetSymbolAddress((void**)&qwh, g_qwh); cudaGetSymbolAddress((void**)&qwl, g_qwl);
    cudaGetSymbolAddress((void**)&pwh, g_pwh); cudaGetSymbolAddress((void**)&pwl, g_pwl);
    cudaGetSymbolAddress((void**)&f1h, g_f1h); cudaGetSymbolAddress((void**)&f1l, g_f1l);
    cudaGetSymbolAddress((void**)&f2h, g_f2h); cudaGetSymbolAddress((void**)&f2l, g_f2l);
    cudaGetSymbolAddress((void**)&qh,  g_qh);  cudaGetSymbolAddress((void**)&ql,  g_ql);
    cudaGetSymbolAddress((void**)&vth, g_vth); cudaGetSymbolAddress((void**)&vtl, g_vtl);
    cudaGetSymbolAddress((void**)&aoh, g_aoh); cudaGetSymbolAddress((void**)&aol, g_aol);
    cudaGetSymbolAddress((void**)&hh,  g_hh);  cudaGetSymbolAddress((void**)&hl,  g_hl);
    cudaGetSymbolAddress((void**)&x1,  g_x1);
    cudaGetSymbolAddress((void**)&stats, g_stats);

    // weight splits
    split_kernel<<<3 * C * C / 4 / 256, 256>>>(qkv_w, qwh, qwl, 3 * C * C / 4);
    split_kernel<<<C * C / 4 / 256, 256>>>(proj_w, pwh, pwl, C * C / 4);
    split_kernel<<<DFF * C / 4 / 256, 256>>>(fc1_w, f1h, f1l, DFF * C / 4);
    split_kernel<<<C * DFF / 4 / 256, 256>>>(fc2_w, f2h, f2l, C * DFF / 4);

    // 1) ln1 -> xn (hi/lo)
    ln_split<<<BNR, 256>>>(x, ln1_g, ln1_b, xnh, xnl);
    // 2) qkv = xn @ qkv_w^T -> split
    hgemm<128,1><<<dim3(24, 32, 1), 256, SMB128>>>(
        xnh, xnl, C, 0, 0, qwh, qwl, C, 0, 0,
        nullptr, qh, ql, 3 * C, 0, 0, C, nullptr, nullptr);
    // 3) fused scores + masked online-softmax stats (raw scores -> out_attn)
    scores_stats<<<dim3(16, 32), 256, SS_SMEM>>>(qh, ql, mask, out_attn, stats);
    // 4) V transpose (per-head [D, N] hi/lo)
    vtrans<<<dim3(N / 32, 1, B * H), 256>>>(qh, ql, vth, vtl);
    // 5) av: normalize in-place (raw -> attn fp32) + attn @ V -> split
    av_gemm<<<dim3(16, 1, 32), 256, SMB_AV>>>(out_attn, stats, vth, vtl, aoh, aol);
    // 6) x1 = x + ao @ proj_w^T + proj_b
    hgemm<128,2><<<dim3(8, 32, 1), 256, SMB128>>>(
        aoh, aol, C, 0, 0, pwh, pwl, C, 0, 0,
        x1, nullptr, nullptr, C, 0, 0, C, proj_b, x);
    // 7) ln2 -> xn (hi/lo)
    ln_split<<<BNR, 256>>>(x1, ln2_g, ln2_b, xnh, xnl);
    // 8) h = gelu(xn @ fc1_w^T + fc1_b) -> split
    hgemm<128,3><<<dim3(32, 32, 1), 256, SMB128>>>(
        xnh, xnl, C, 0, 0, f1h, f1l, C, 0, 0,
        nullptr, hh, hl, DFF, 0, 0, C, fc1_b, nullptr);
    // 9) out_x = x1 + h @ fc2_w^T + fc2_b
    hgemm<128,2><<<dim3(8, 32, 1), 256, SMB128>>>(
        hh, hl, DFF, 0, 0, f2h, f2l, DFF, 0, 0,
        out_x, nullptr, nullptr, C, 0, 0, DFF, fc2_b, x1);
}

// round 9
// speedup vs baseline: 1.7769x; 1.7769x over previous
#include <cuda_runtime.h>
#include <cuda_bf16.h>
#include <math.h>
#include <stdint.h>

constexpr int B = 2, N = 2048, C = 1024, H = 16, D = 64, DFF = 4096;
constexpr int BNR = B * N;   // 4096
constexpr float EPS = 1e-5f;

// ---------------- low-level helpers (family-generic PTX: no tcgen05) -------
__device__ __forceinline__ uint32_t smem_u32(const void* p) {
    uint32_t a;
    asm("{ .reg .u64 t; cvta.to.shared.u64 t, %1; cvt.u32.u64 %0, t; }" : "=r"(a) : "l"(p));
    return a;
}
__device__ __forceinline__ void cpasync16(uint32_t dst, const void* src) {
    asm volatile("cp.async.cg.shared.global [%0], [%1], 16;" :: "r"(dst), "l"(src));
}
__device__ __forceinline__ void cp_commit() {
    asm volatile("cp.async.commit_group;");
}
template<int Nw>
__device__ __forceinline__ void cp_wait() {
    asm volatile("cp.async.wait_group %0;" :: "n"(Nw));
}
__device__ __forceinline__ void ldsm4(uint32_t* r, uint32_t addr) {
    asm volatile("ldmatrix.sync.aligned.m8n8.x4.shared.b16 {%0,%1,%2,%3}, [%4];"
        : "=r"(r[0]), "=r"(r[1]), "=r"(r[2]), "=r"(r[3]) : "r"(addr));
}
__device__ __forceinline__ void mma16816(float* d, const uint32_t* a, const uint32_t* b) {
    asm volatile("mma.sync.aligned.m16n8k16.row.col.f32.bf16.bf16.f32 "
        "{%0,%1,%2,%3}, {%4,%5,%6,%7}, {%8,%9}, {%0,%1,%2,%3};"
        : "+f"(d[0]), "+f"(d[1]), "+f"(d[2]), "+f"(d[3])
        : "r"(a[0]), "r"(a[1]), "r"(a[2]), "r"(a[3]), "r"(b[0]), "r"(b[1]));
}
__device__ __forceinline__ float gelu_exact(float v) {
    return 0.5f * v * (1.0f + erff(v * 0.70710678118654752f));
}
__device__ __forceinline__ void split2store(__nv_bfloat16* hi, __nv_bfloat16* lo,
                                            float v0, float v1) {
    __nv_bfloat16 h0 = __float2bfloat16(v0), h1 = __float2bfloat16(v1);
    __nv_bfloat162 hh(h0, h1);
    __nv_bfloat162 ll(__float2bfloat16(v0 - __bfloat162float(h0)),
                      __float2bfloat16(v1 - __bfloat162float(h1)));
    *reinterpret_cast<__nv_bfloat162*>(hi) = hh;
    *reinterpret_cast<__nv_bfloat162*>(lo) = ll;
}
__device__ __forceinline__ uint2 cvt_hi2(float4 v) {
    __nv_bfloat162 a(__float2bfloat16(v.x), __float2bfloat16(v.y));
    __nv_bfloat162 b(__float2bfloat16(v.z), __float2bfloat16(v.w));
    return make_uint2(*(uint32_t*)&a, *(uint32_t*)&b);
}
__device__ __forceinline__ uint2 cvt_lo2(float4 v, uint2 hi) {
    __nv_bfloat162 ha = *(__nv_bfloat162*)&hi.x, hb = *(__nv_bfloat162*)&hi.y;
    __nv_bfloat162 a(__float2bfloat16(v.x - __bfloat162float(ha.x)),
                     __float2bfloat16(v.y - __bfloat162float(ha.y)));
    __nv_bfloat162 b(__float2bfloat16(v.z - __bfloat162float(hb.x)),
                     __float2bfloat16(v.w - __bfloat162float(hb.y)));
    return make_uint2(*(uint32_t*)&a, *(uint32_t*)&b);
}

// ---------------- scratch ----------------
#define GA __device__ __align__(256)
GA __nv_bfloat16 g_xnh[BNR * C],      g_xnl[BNR * C];
GA __nv_bfloat16 g_qwh[3 * C * C],    g_qwl[3 * C * C];
GA __nv_bfloat16 g_pwh[C * C],        g_pwl[C * C];
GA __nv_bfloat16 g_f1h[DFF * C],      g_f1l[DFF * C];
GA __nv_bfloat16 g_f2h[C * DFF],      g_f2l[C * DFF];
GA __nv_bfloat16 g_qh[BNR * 3 * C],   g_ql[BNR * 3 * C];
GA __nv_bfloat16 g_vth[B * H * D * N], g_vtl[B * H * D * N];
GA __nv_bfloat16 g_aoh[BNR * C],      g_aol[BNR * C];
GA __nv_bfloat16 g_hh[BNR * DFF],     g_hl[BNR * DFF];
GA float g_x1[BNR * C];

// ---------------- fp32 -> (hi,lo) bf16 split ----------------
__global__ void split_kernel(const float* __restrict__ s, __nv_bfloat16* __restrict__ hi,
                             __nv_bfloat16* __restrict__ lo, int n4) {
    int i = blockIdx.x * 256 + threadIdx.x;
    if (i >= n4) return;
    float4 v = reinterpret_cast<const float4*>(s)[i];
    uint2 h = cvt_hi2(v);
    uint2 l = cvt_lo2(v, h);
    reinterpret_cast<uint2*>(hi)[i] = h;
    reinterpret_cast<uint2*>(lo)[i] = l;
}

// ---------------- LayerNorm -> split ----------------
__global__ void ln_split(const float* __restrict__ x, const float* __restrict__ g,
                         const float* __restrict__ b, __nv_bfloat16* __restrict__ hi,
                         __nv_bfloat16* __restrict__ lo) {
    const int row = blockIdx.x, tid = threadIdx.x;
    const float* xr = x + (size_t)row * C;
    __shared__ float sd[C];
    __shared__ float red[256];
    float ls = 0.f;
    for (int i = tid; i < C; i += 256) { float v = xr[i]; sd[i] = v; ls += v; }
    red[tid] = ls; __syncthreads();
    for (int s = 128; s > 0; s >>= 1) { if (tid < s) red[tid] += red[tid + s]; __syncthreads(); }
    const float mu = red[0] * (1.0f / C); __syncthreads();
    float lv = 0.f;
    for (int i = tid; i < C; i += 256) { float d = sd[i] - mu; lv += d * d; }
    red[tid] = lv; __syncthreads();
    for (int s = 128; s > 0; s >>= 1) { if (tid < s) red[tid] += red[tid + s]; __syncthreads(); }
    const float rstd = rsqrtf(red[0] * (1.0f / C) + EPS);
    for (int i = tid; i < C; i += 256) {
        float v = (sd[i] - mu) * rstd * g[i] + b[i];
        __nv_bfloat16 h = __float2bfloat16(v);
        hi[(size_t)row * C + i] = h;
        lo[(size_t)row * C + i] = __float2bfloat16(v - __bfloat162float(h));
    }
}

// ---------------- masked softmax (in-place fp32) ----------------
__global__ void softmax_kernel(float* __restrict__ attn, const int* __restrict__ mask) {
    const long long row = blockIdx.x;
    const int b = (int)(row / ((long long)H * N));
    float* p = attn + row * (long long)N;
    const int* mr = mask + (size_t)b * N;
    const int tid = threadIdx.x;
    __shared__ float red[256];
    float vals[8];
    float lmax = -INFINITY;
    #pragma unroll
    for (int j = 0; j < 8; j++) {
        int i = tid + j * 256;
        float v = mr[i] ? p[i] : -INFINITY;
        vals[j] = v; lmax = fmaxf(lmax, v);
    }
    red[tid] = lmax; __syncthreads();
    for (int s = 128; s > 0; s >>= 1) { if (tid < s) red[tid] = fmaxf(red[tid], red[tid + s]); __syncthreads(); }
    const float rm = red[0]; __syncthreads();
    float ls = 0.f;
    #pragma unroll
    for (int j = 0; j < 8; j++) { float e = __expf(vals[j] - rm); vals[j] = e; ls += e; }
    red[tid] = ls; __syncthreads();
    for (int s = 128; s > 0; s >>= 1) { if (tid < s) red[tid] += red[tid + s]; __syncthreads(); }
    const float inv = 1.0f / red[0];
    #pragma unroll
    for (int j = 0; j < 8; j++) p[tid + j * 256] = vals[j] * inv;
}

// ---------------- V transpose: qkv[.,2C+h*64+d] -> vt[b,h,d,n] ----------------
__global__ void vtrans(const __nv_bfloat16* __restrict__ qh, const __nv_bfloat16* __restrict__ ql,
                       __nv_bfloat16* __restrict__ vh, __nv_bfloat16* __restrict__ vl) {
    const int z = blockIdx.z, b = z >> 4, h = z & 15;
    const int n0 = blockIdx.x * 32, tid = threadIdx.x;
    __shared__ __nv_bfloat16 sh[64][33], sl[64][33];
    for (int i = tid; i < 2048; i += 256) {
        int r = i >> 6, d = i & 63;
        size_t o = (size_t)(b * N + n0 + r) * (3 * C) + 2 * C + h * 64 + d;
        sh[d][r] = qh[o]; sl[d][r] = ql[o];
    }
    __syncthreads();
    for (int i = tid; i < 2048; i += 256) {
        int d = i >> 5, c = i & 31;
        size_t o = (size_t)z * D * N + (size_t)d * N + n0 + c;
        vh[o] = sh[d][c]; vl[o] = sl[d][c];
    }
}

// ===========================================================================
// HMMA GEMM (NT), 2-stage cp.async, 80 KB smem. __launch_bounds__(256, 2)
// forces regs <= 128 so 2 CTAs/SM are guaranteed (this round's experiment).
// EPI: 0 = *0.125 -> fp32   1 = split -> hi/lo   2 = +bias+resid -> fp32
//      3 = gelu(+bias) -> split hi/lo
// ===========================================================================
template<int BN_, int EPI>
__global__ void __launch_bounds__(256, 2) hgemm(
    const __nv_bfloat16* __restrict__ Ah, const __nv_bfloat16* __restrict__ Al,
    int lda, long long sAb, long long sAh,
    const __nv_bfloat16* __restrict__ Bh, const __nv_bfloat16* __restrict__ Bl,
    int ldb, long long sBb, long long sBh,
    float* __restrict__ Cf, __nv_bfloat16* __restrict__ Chi, __nv_bfloat16* __restrict__ Clo,
    int ldc, long long sCb, long long sCh,
    int K, const float* __restrict__ bias, const float* __restrict__ resid) {
    extern __shared__ char smem[];
    constexpr int ROWB = 80;
    constexpr int ATILE = 128 * ROWB;
    constexpr int STAGE = 2 * ATILE + 2 * BN_ * ROWB;
    constexpr int WTN = BN_ / 2;
    constexpr int NA = WTN / 8;

    const int tid = threadIdx.x, lane = tid & 31, wid = tid >> 5;
    const int wm = wid & 3, wn = wid >> 2;
    const int z = blockIdx.z, bz = z >> 4, hz = z & 15;
    Ah += (size_t)bz * sAb + (size_t)hz * sAh;
    Al += (size_t)bz * sAb + (size_t)hz * sAh;
    Bh += (size_t)bz * sBb + (size_t)hz * sBh;
    Bl += (size_t)bz * sBb + (size_t)hz * sBh;
    const size_t coff = (size_t)bz * sCb + (size_t)hz * sCh;
    const int m0 = blockIdx.y * 128, n0 = blockIdx.x * BN_;
    const uint32_t sbase = smem_u32(smem);

    auto load_stage = [&](int s, int k0) {
        const uint32_t st = sbase + s * STAGE;
        #pragma unroll
        for (int i = tid; i < 512; i += 256) {
            int r = i >> 2, c4 = i & 3;
            uint32_t d = st + r * ROWB + c4 * 16;
            cpasync16(d,         Ah + (size_t)(m0 + r) * lda + k0 + c4 * 8);
            cpasync16(d + ATILE, Al + (size_t)(m0 + r) * lda + k0 + c4 * 8);
        }
        #pragma unroll
        for (int i = tid; i < BN_ * 4; i += 256) {
            int r = i >> 2, c4 = i & 3;
            uint32_t d = st + 2 * ATILE + r * ROWB + c4 * 16;
            cpasync16(d,              Bh + (size_t)(n0 + r) * ldb + k0 + c4 * 8);
            cpasync16(d + BN_ * ROWB, Bl + (size_t)(n0 + r) * ldb + k0 + c4 * 8);
        }
        cp_commit();
    };

    float acc[2][NA][4];
    #pragma unroll
    for (int a = 0; a < 2; a++)
        #pragma unroll
        for (int b2 = 0; b2 < NA; b2++)
            #pragma unroll
            for (int c = 0; c < 4; c++) acc[a][b2][c] = 0.f;

    const int nch = K >> 5;
    load_stage(0, 0);
    for (int ch = 0; ch < nch; ch++) {
        if (ch + 1 < nch) { load_stage((ch + 1) & 1, (ch + 1) << 5); cp_wait<1>(); }
        else cp_wait<0>();
        __syncthreads();

        const uint32_t st  = sbase + (ch & 1) * STAGE;
        const uint32_t bst = st + 2 * ATILE;
        const int arow = wm * 32 + (lane & 15);
        const int acolb = ((lane >> 4) << 4);
        const int brow = (lane & 7) + ((lane >> 4) << 3);
        const int bcolb = (((lane >> 3) & 1) << 4);
        #pragma unroll
        for (int ks = 0; ks < 2; ks++) {
            uint32_t afh[2][4], afl[2][4];
            #pragma unroll
            for (int ma = 0; ma < 2; ma++) {
                uint32_t ad = st + (arow + ma * 16) * ROWB + ks * 32 + acolb;
                ldsm4(afh[ma], ad);
                ldsm4(afl[ma], ad + ATILE);
            }
            uint32_t bfh[NA][2], bfl[NA][2];
            #pragma unroll
            for (int p = 0; p < NA / 2; p++) {
                uint32_t r4[4];
                uint32_t bd = bst + (wn * WTN + p * 16 + brow) * ROWB + ks * 32 + bcolb;
                ldsm4(r4, bd);
                bfh[2*p][0] = r4[0]; bfh[2*p][1] = r4[1];
                bfh[2*p+1][0] = r4[2]; bfh[2*p+1][1] = r4[3];
                ldsm4(r4, bd + BN_ * ROWB);
                bfl[2*p][0] = r4[0]; bfl[2*p][1] = r4[1];
                bfl[2*p+1][0] = r4[2]; bfl[2*p+1][1] = r4[3];
            }
            #pragma unroll
            for (int ma = 0; ma < 2; ma++)
                #pragma unroll
                for (int na = 0; na < NA; na++) {
                    mma16816(acc[ma][na], afh[ma], bfh[na]);
                    mma16816(acc[ma][na], afh[ma], bfl[na]);
                    mma16816(acc[ma][na], afl[ma], bfh[na]);
                }
        }
        __syncthreads();
    }

    #pragma unroll
    for (int ma = 0; ma < 2; ma++)
        #pragma unroll
        for (int na = 0; na < NA; na++) {
            const int gr0 = m0 + wm * 32 + ma * 16 + (lane >> 2);
            const int gc  = n0 + wn * WTN + na * 8 + ((lane & 3) << 1);
            #pragma unroll
            for (int h2 = 0; h2 < 2; h2++) {
                const int gr = gr0 + h2 * 8;
                float v0 = acc[ma][na][h2 * 2], v1 = acc[ma][na][h2 * 2 + 1];
                const size_t o = coff + (size_t)gr * ldc + gc;
                if (EPI == 0) {
                    *reinterpret_cast<float2*>(Cf + o) = make_float2(v0 * 0.125f, v1 * 0.125f);
                }
                if (EPI == 1) split2store(Chi + o, Clo + o, v0, v1);
                if (EPI == 2) {
                    *reinterpret_cast<float2*>(Cf + o) = make_float2(
                        v0 + bias[gc]     + resid[(size_t)gr * ldc + gc],
                        v1 + bias[gc + 1] + resid[(size_t)gr * ldc + gc + 1]);
                }
                if (EPI == 3) {
                    float t0 = gelu_exact(v0 + bias[gc]);
                    float t1 = gelu_exact(v1 + bias[gc + 1]);
                    split2store(Chi + o, Clo + o, t0, t1);
                }
            }
        }
}

// ===========================================================================
// attn @ V: A = fp32 attn [N,N] per head, converted to bf16 hi/lo in regs
// while staging to SMEM. 2-stage, 60 KB smem, __launch_bounds__(256, 2).
// ===========================================================================
__global__ void __launch_bounds__(256, 2) av_gemm(
    const float* __restrict__ attn,
    const __nv_bfloat16* __restrict__ Vh, const __nv_bfloat16* __restrict__ Vl,
    __nv_bfloat16* __restrict__ Ohi, __nv_bfloat16* __restrict__ Olo) {
    extern __shared__ char smem[];
    constexpr int ROWB = 80;
    constexpr int ATILE = 128 * ROWB;             // 10240
    constexpr int BTILE = 64 * ROWB;              // 5120
    constexpr int STAGE = 2 * ATILE + 2 * BTILE;  // 30720
    constexpr int NA = 4;

    const int tid = threadIdx.x, lane = tid & 31, wid = tid >> 5;
    const int wm = wid & 3, wn = wid >> 2;
    const int z = blockIdx.z, bz = z >> 4, hz = z & 15;
    const int m0 = blockIdx.x * 128;
    const float* Ab = attn + (size_t)z * N * N;
    const __nv_bfloat16* Bh = Vh + (size_t)z * D * N;
    const __nv_bfloat16* Bl = Vl + (size_t)z * D * N;
    const uint32_t sbase = smem_u32(smem);

    float4 areg[4];
    auto ldg_A = [&](int k0) {
        #pragma unroll
        for (int j = 0; j < 4; j++) {
            int i = tid + j * 256;
            int r = i >> 3, c4 = i & 7;
            areg[j] = *reinterpret_cast<const float4*>(Ab + (size_t)(m0 + r) * N + k0 + c4 * 4);
        }
    };
    auto sts_A = [&](int s) {
        #pragma unroll
        for (int j = 0; j < 4; j++) {
            int i = tid + j * 256;
            int r = i >> 3, c4 = i & 7;
            uint2 h = cvt_hi2(areg[j]);
            uint2 l = cvt_lo2(areg[j], h);
            *reinterpret_cast<uint2*>(smem + s * STAGE + r * ROWB + c4 * 8) = h;
            *reinterpret_cast<uint2*>(smem + s * STAGE + ATILE + r * ROWB + c4 * 8) = l;
        }
    };
    auto ld_B = [&](int s, int k0) {
        const uint32_t st = sbase + s * STAGE + 2 * ATILE;
        {
            int i = tid;
            int r = i >> 2, c4 = i & 3;
            uint32_t d = st + r * ROWB + c4 * 16;
            cpasync16(d,         Bh + (size_t)r * N + k0 + c4 * 8);
            cpasync16(d + BTILE, Bl + (size_t)r * N + k0 + c4 * 8);
        }
        cp_commit();
    };

    float acc[2][NA][4];
    #pragma unroll
    for (int a = 0; a < 2; a++)
        #pragma unroll
        for (int b2 = 0; b2 < NA; b2++)
            #pragma unroll
            for (int c = 0; c < 4; c++) acc[a][b2][c] = 0.f;

    constexpr int nch = N / 32;    // 64
    ldg_A(0);
    sts_A(0);
    ld_B(0, 0);
    ldg_A(32);                     // regs now hold A(1)

    for (int ch = 0; ch < nch; ch++) {
        if (ch + 1 < nch) {
            sts_A((ch + 1) & 1);
            ld_B((ch + 1) & 1, (ch + 1) << 5);
        }
        if (ch + 2 < nch) ldg_A((ch + 2) << 5);
        if (ch + 1 < nch) cp_wait<1>(); else cp_wait<0>();
        __syncthreads();

        const uint32_t st  = sbase + (ch & 1) * STAGE;
        const uint32_t bst = st + 2 * ATILE;
        const int arow = wm * 32 + (lane & 15);
        const int acolb = ((lane >> 4) << 4);
        const int brow = (lane & 7) + ((lane >> 4) << 3);
        const int bcolb = (((lane >> 3) & 1) << 4);
        #pragma unroll
        for (int ks = 0; ks < 2; ks++) {
            uint32_t afh[2][4], afl[2][4];
            #pragma unroll
            for (int ma = 0; ma < 2; ma++) {
                uint32_t ad = st + (arow + ma * 16) * ROWB + ks * 32 + acolb;
                ldsm4(afh[ma], ad);
                ldsm4(afl[ma], ad + ATILE);
            }
            uint32_t bfh[NA][2], bfl[NA][2];
            #pragma unroll
            for (int p = 0; p < NA / 2; p++) {
                uint32_t r4[4];
                uint32_t bd = bst + (wn * 32 + p * 16 + brow) * ROWB + ks * 32 + bcolb;
                ldsm4(r4, bd);
                bfh[2*p][0] = r4[0]; bfh[2*p][1] = r4[1];
                bfh[2*p+1][0] = r4[2]; bfh[2*p+1][1] = r4[3];
                ldsm4(r4, bd + BTILE);
                bfl[2*p][0] = r4[0]; bfl[2*p][1] = r4[1];
                bfl[2*p+1][0] = r4[2]; bfl[2*p+1][1] = r4[3];
            }
            #pragma unroll
            for (int ma = 0; ma < 2; ma++)
                #pragma unroll
                for (int na = 0; na < NA; na++) {
                    mma16816(acc[ma][na], afh[ma], bfh[na]);
                    mma16816(acc[ma][na], afh[ma], bfl[na]);
                    mma16816(acc[ma][na], afl[ma], bfh[na]);
                }
        }
        __syncthreads();
    }

    #pragma unroll
    for (int ma = 0; ma < 2; ma++)
        #pragma unroll
        for (int na = 0; na < NA; na++) {
            const int lr0 = wm * 32 + ma * 16 + (lane >> 2);
            const int gc  = hz * 64 + wn * 32 + na * 8 + ((lane & 3) << 1);
            #pragma unroll
            for (int h2 = 0; h2 < 2; h2++) {
                const size_t o = (size_t)(bz * N + m0 + lr0 + h2 * 8) * C + gc;
                split2store(Ohi + o, Olo + o, acc[ma][na][h2 * 2], acc[ma][na][h2 * 2 + 1]);
            }
        }
}

constexpr int SMB128 = 2 * (2 * 128 * 80 + 2 * 128 * 80);  // 81920
constexpr int SMB_AV = 2 * (2 * 128 * 80 + 2 * 64 * 80);   // 61440

// ---------------- host ----------------
extern "C" void kernel_launch(void* const* d_in, const int* in_sizes, int n_in,
                              void* d_out, int out_size) {
    const float* x      = (const float*)d_in[0];
    const int*   mask   = (const int*)  d_in[1];
    const float* qkv_w  = (const float*)d_in[2];
    const float* proj_w = (const float*)d_in[3];
    const float* proj_b = (const float*)d_in[4];
    const float* ln1_g  = (const float*)d_in[5];
    const float* ln1_b  = (const float*)d_in[6];
    const float* ln2_g  = (const float*)d_in[7];
    const float* ln2_b  = (const float*)d_in[8];
    const float* fc1_w  = (const float*)d_in[9];
    const float* fc1_b  = (const float*)d_in[10];
    const float* fc2_w  = (const float*)d_in[11];
    const float* fc2_b  = (const float*)d_in[12];
    float* out_x    = (float*)d_out;
    float* out_attn = out_x + (size_t)B * N * C;

    cudaFuncSetAttribute(hgemm<128,0>, cudaFuncAttributeMaxDynamicSharedMemorySize, SMB128);
    cudaFuncSetAttribute(hgemm<128,1>, cudaFuncAttributeMaxDynamicSharedMemorySize, SMB128);
    cudaFuncSetAttribute(hgemm<128,2>, cudaFuncAttributeMaxDynamicSharedMemorySize, SMB128);
    cudaFuncSetAttribute(hgemm<128,3>, cudaFuncAttributeMaxDynamicSharedMemorySize, SMB128);
    cudaFuncSetAttribute(av_gemm,      cudaFuncAttributeMaxDynamicSharedMemorySize, SMB_AV);

    __nv_bfloat16 *xnh, *xnl, *qwh, *qwl, *pwh, *pwl, *f1h, *f1l, *f2h, *f2l;
    __nv_bfloat16 *qh, *ql, *vth, *vtl, *aoh, *aol, *hh, *hl;
    float* x1;
    cudaGetSymbolAddress((void**)&xnh, g_xnh); cudaGetSymbolAddress((void**)&xnl, g_xnl);
    cudaGetSymbolAddress((void**)&qwh, g_qwh); cudaGetSymbolAddress((void**)&qwl, g_qwl);
    cudaGetSymbolAddress((void**)&pwh, g_pwh); cudaGetSymbolAddress((void**)&pwl, g_pwl);
    cudaGetSymbolAddress((void**)&f1h, g_f1h); cudaGetSymbolAddress((void**)&f1l, g_f1l);
    cudaGetSymbolAddress((void**)&f2h, g_f2h); cudaGetSymbolAddress((void**)&f2l, g_f2l);
    cudaGetSymbolAddress((void**)&qh,  g_qh);  cudaGetSymbolAddress((void**)&ql,  g_ql);
    cudaGetSymbolAddress((void**)&vth, g_vth); cudaGetSymbolAddress((void**)&vtl, g_vtl);
    cudaGetSymbolAddress((void**)&aoh, g_aoh); cudaGetSymbolAddress((void**)&aol, g_aol);
    cudaGetSymbolAddress((void**)&hh,  g_hh);  cudaGetSymbolAddress((void**)&hl,  g_hl);
    cudaGetSymbolAddress((void**)&x1,  g_x1);

    // weight splits
    split_kernel<<<3 * C * C / 4 / 256, 256>>>(qkv_w, qwh, qwl, 3 * C * C / 4);
    split_kernel<<<C * C / 4 / 256, 256>>>(proj_w, pwh, pwl, C * C / 4);
    split_kernel<<<DFF * C / 4 / 256, 256>>>(fc1_w, f1h, f1l, DFF * C / 4);
    split_kernel<<<C * DFF / 4 / 256, 256>>>(fc2_w, f2h, f2l, C * DFF / 4);

    // 1) ln1 -> xn (hi/lo)
    ln_split<<<BNR, 256>>>(x, ln1_g, ln1_b, xnh, xnl);
    // 2) qkv = xn @ qkv_w^T -> split
    hgemm<128,1><<<dim3(24, 32, 1), 256, SMB128>>>(
        xnh, xnl, C, 0, 0, qwh, qwl, C, 0, 0,
        nullptr, qh, ql, 3 * C, 0, 0, C, nullptr, nullptr);
    // 3) scores = 0.125 * Q @ K^T -> out_attn fp32 (batched over B*H)
    hgemm<128,0><<<dim3(16, 16, 32), 256, SMB128>>>(
        qh, ql, 3 * C, (long long)N * 3 * C, 64,
        qh + C, ql + C, 3 * C, (long long)N * 3 * C, 64,
        out_attn, nullptr, nullptr, N, (long long)H * N * N, (long long)N * N,
        64, nullptr, nullptr);
    // 4) masked softmax (in-place, fp32 only)
    softmax_kernel<<<B * H * N, 256>>>(out_attn, mask);
    // 5) V transpose (per-head [D, N] hi/lo)
    vtrans<<<dim3(N / 32, 1, B * H), 256>>>(qh, ql, vth, vtl);
    // 6) ao = attn @ V (reads fp32 attn, converts in-kernel) -> split
    av_gemm<<<dim3(16, 1, 32), 256, SMB_AV>>>(out_attn, vth, vtl, aoh, aol);
    // 7) x1 = x + ao @ proj_w^T + proj_b
    hgemm<128,2><<<dim3(8, 32, 1), 256, SMB128>>>(
        aoh, aol, C, 0, 0, pwh, pwl, C, 0, 0,
        x1, nullptr, nullptr, C, 0, 0, C, proj_b, x);
    // 8) ln2 -> xn (hi/lo)
    ln_split<<<BNR, 256>>>(x1, ln2_g, ln2_b, xnh, xnl);
    // 9) h = gelu(xn @ fc1_w^T + fc1_b) -> split
    hgemm<128,3><<<dim3(32, 32, 1), 256, SMB128>>>(
        xnh, xnl, C, 0, 0, f1h, f1l, C, 0, 0,
        nullptr, hh, hl, DFF, 0, 0, C, fc1_b, nullptr);
    // 10) out_x = x1 + h @ fc2_w^T + fc2_b
    hgemm<128,2><<<dim3(8, 32, 1), 256, SMB128>>>(
        hh, hl, DFF, 0, 0, f2h, f2l, DFF, 0, 0,
        out_x, nullptr, nullptr, C, 0, 0, DFF, fc2_b, x1);
}

// round 10
// speedup vs baseline: 1.7879x; 1.0062x over previous
#include <cuda_runtime.h>
#include <cuda_bf16.h>
#include <math.h>
#include <stdint.h>

constexpr int B = 2, N = 2048, C = 1024, H = 16, D = 64, DFF = 4096;
constexpr int BNR = B * N;   // 4096
constexpr float EPS = 1e-5f;

// ---------------- low-level helpers (family-generic PTX: no tcgen05) -------
__device__ __forceinline__ uint32_t smem_u32(const void* p) {
    uint32_t a;
    asm("{ .reg .u64 t; cvta.to.shared.u64 t, %1; cvt.u32.u64 %0, t; }" : "=r"(a) : "l"(p));
    return a;
}
__device__ __forceinline__ void cpasync16(uint32_t dst, const void* src) {
    asm volatile("cp.async.cg.shared.global [%0], [%1], 16;" :: "r"(dst), "l"(src));
}
__device__ __forceinline__ void cp_commit() {
    asm volatile("cp.async.commit_group;");
}
template<int Nw>
__device__ __forceinline__ void cp_wait() {
    asm volatile("cp.async.wait_group %0;" :: "n"(Nw));
}
__device__ __forceinline__ void ldsm4(uint32_t* r, uint32_t addr) {
    asm volatile("ldmatrix.sync.aligned.m8n8.x4.shared.b16 {%0,%1,%2,%3}, [%4];"
        : "=r"(r[0]), "=r"(r[1]), "=r"(r[2]), "=r"(r[3]) : "r"(addr));
}
__device__ __forceinline__ void mma16816(float* d, const uint32_t* a, const uint32_t* b) {
    asm volatile("mma.sync.aligned.m16n8k16.row.col.f32.bf16.bf16.f32 "
        "{%0,%1,%2,%3}, {%4,%5,%6,%7}, {%8,%9}, {%0,%1,%2,%3};"
        : "+f"(d[0]), "+f"(d[1]), "+f"(d[2]), "+f"(d[3])
        : "r"(a[0]), "r"(a[1]), "r"(a[2]), "r"(a[3]), "r"(b[0]), "r"(b[1]));
}
__device__ __forceinline__ float gelu_exact(float v) {
    return 0.5f * v * (1.0f + erff(v * 0.70710678118654752f));
}
__device__ __forceinline__ void split2store(__nv_bfloat16* hi, __nv_bfloat16* lo,
                                            float v0, float v1) {
    __nv_bfloat16 h0 = __float2bfloat16(v0), h1 = __float2bfloat16(v1);
    __nv_bfloat162 hh(h0, h1);
    __nv_bfloat162 ll(__float2bfloat16(v0 - __bfloat162float(h0)),
                      __float2bfloat16(v1 - __bfloat162float(h1)));
    *reinterpret_cast<__nv_bfloat162*>(hi) = hh;
    *reinterpret_cast<__nv_bfloat162*>(lo) = ll;
}
__device__ __forceinline__ uint2 cvt_hi2(float4 v) {
    __nv_bfloat162 a(__float2bfloat16(v.x), __float2bfloat16(v.y));
    __nv_bfloat162 b(__float2bfloat16(v.z), __float2bfloat16(v.w));
    return make_uint2(*(uint32_t*)&a, *(uint32_t*)&b);
}
__device__ __forceinline__ uint2 cvt_lo2(float4 v, uint2 hi) {
    __nv_bfloat162 ha = *(__nv_bfloat162*)&hi.x, hb = *(__nv_bfloat162*)&hi.y;
    __nv_bfloat162 a(__float2bfloat16(v.x - __bfloat162float(ha.x)),
                     __float2bfloat16(v.y - __bfloat162float(ha.y)));
    __nv_bfloat162 b(__float2bfloat16(v.z - __bfloat162float(hb.x)),
                     __float2bfloat16(v.w - __bfloat162float(hb.y)));
    return make_uint2(*(uint32_t*)&a, *(uint32_t*)&b);
}

// ---------------- scratch ----------------
#define GA __device__ __align__(256)
GA __nv_bfloat16 g_xnh[BNR * C],      g_xnl[BNR * C];
GA __nv_bfloat16 g_qwh[3 * C * C],    g_qwl[3 * C * C];
GA __nv_bfloat16 g_pwh[C * C],        g_pwl[C * C];
GA __nv_bfloat16 g_f1h[DFF * C],      g_f1l[DFF * C];
GA __nv_bfloat16 g_f2h[C * DFF],      g_f2l[C * DFF];
GA __nv_bfloat16 g_qh[BNR * 3 * C],   g_ql[BNR * 3 * C];
GA __nv_bfloat16 g_vth[B * H * D * N], g_vtl[B * H * D * N];
GA __nv_bfloat16 g_aoh[BNR * C],      g_aol[BNR * C];
GA __nv_bfloat16 g_hh[BNR * DFF],     g_hl[BNR * DFF];
GA float g_x1[BNR * C];

// ---------------- fp32 -> (hi,lo) bf16 split ----------------
__global__ void split_kernel(const float* __restrict__ s, __nv_bfloat16* __restrict__ hi,
                             __nv_bfloat16* __restrict__ lo, int n4) {
    int i = blockIdx.x * 256 + threadIdx.x;
    if (i >= n4) return;
    float4 v = reinterpret_cast<const float4*>(s)[i];
    uint2 h = cvt_hi2(v);
    uint2 l = cvt_lo2(v, h);
    reinterpret_cast<uint2*>(hi)[i] = h;
    reinterpret_cast<uint2*>(lo)[i] = l;
}

// ---------------- LayerNorm -> split ----------------
__global__ void ln_split(const float* __restrict__ x, const float* __restrict__ g,
                         const float* __restrict__ b, __nv_bfloat16* __restrict__ hi,
                         __nv_bfloat16* __restrict__ lo) {
    const int row = blockIdx.x, tid = threadIdx.x;
    const float* xr = x + (size_t)row * C;
    __shared__ float sd[C];
    __shared__ float red[256];
    float ls = 0.f;
    for (int i = tid; i < C; i += 256) { float v = xr[i]; sd[i] = v; ls += v; }
    red[tid] = ls; __syncthreads();
    for (int s = 128; s > 0; s >>= 1) { if (tid < s) red[tid] += red[tid + s]; __syncthreads(); }
    const float mu = red[0] * (1.0f / C); __syncthreads();
    float lv = 0.f;
    for (int i = tid; i < C; i += 256) { float d = sd[i] - mu; lv += d * d; }
    red[tid] = lv; __syncthreads();
    for (int s = 128; s > 0; s >>= 1) { if (tid < s) red[tid] += red[tid + s]; __syncthreads(); }
    const float rstd = rsqrtf(red[0] * (1.0f / C) + EPS);
    for (int i = tid; i < C; i += 256) {
        float v = (sd[i] - mu) * rstd * g[i] + b[i];
        __nv_bfloat16 h = __float2bfloat16(v);
        hi[(size_t)row * C + i] = h;
        lo[(size_t)row * C + i] = __float2bfloat16(v - __bfloat162float(h));
    }
}

// ---------------- masked softmax (in-place fp32, float4) ----------------
__global__ void softmax_kernel(float* __restrict__ attn, const int* __restrict__ mask) {
    const long long row = blockIdx.x;
    const int b = (int)(row / ((long long)H * N));
    float4* p4 = reinterpret_cast<float4*>(attn + row * (long long)N);
    const int4* mr4 = reinterpret_cast<const int4*>(mask + (size_t)b * N);
    const int tid = threadIdx.x;
    __shared__ float red[256];
    float4 vals[2];
    float lmax = -INFINITY;
    #pragma unroll
    for (int j = 0; j < 2; j++) {
        int i = tid + j * 256;
        float4 v = p4[i];
        int4 m = mr4[i];
        v.x = m.x ? v.x : -INFINITY;
        v.y = m.y ? v.y : -INFINITY;
        v.z = m.z ? v.z : -INFINITY;
        v.w = m.w ? v.w : -INFINITY;
        vals[j] = v;
        lmax = fmaxf(lmax, fmaxf(fmaxf(v.x, v.y), fmaxf(v.z, v.w)));
    }
    red[tid] = lmax; __syncthreads();
    for (int s = 128; s > 0; s >>= 1) { if (tid < s) red[tid] = fmaxf(red[tid], red[tid + s]); __syncthreads(); }
    const float rm = red[0]; __syncthreads();
    float ls = 0.f;
    #pragma unroll
    for (int j = 0; j < 2; j++) {
        float4 v = vals[j];
        v.x = __expf(v.x - rm); v.y = __expf(v.y - rm);
        v.z = __expf(v.z - rm); v.w = __expf(v.w - rm);
        vals[j] = v;
        ls += (v.x + v.y) + (v.z + v.w);
    }
    red[tid] = ls; __syncthreads();
    for (int s = 128; s > 0; s >>= 1) { if (tid < s) red[tid] += red[tid + s]; __syncthreads(); }
    const float inv = 1.0f / red[0];
    #pragma unroll
    for (int j = 0; j < 2; j++) {
        float4 v = vals[j];
        v.x *= inv; v.y *= inv; v.z *= inv; v.w *= inv;
        p4[tid + j * 256] = v;
    }
}

// ---------------- V transpose: qkv[.,2C+h*64+d] -> vt[b,h,d,n] ----------------
__global__ void vtrans(const __nv_bfloat16* __restrict__ qh, const __nv_bfloat16* __restrict__ ql,
                       __nv_bfloat16* __restrict__ vh, __nv_bfloat16* __restrict__ vl) {
    const int z = blockIdx.z, b = z >> 4, h = z & 15;
    const int n0 = blockIdx.x * 32, tid = threadIdx.x;
    __shared__ __nv_bfloat16 sh[64][33], sl[64][33];
    for (int i = tid; i < 2048; i += 256) {
        int r = i >> 6, d = i & 63;
        size_t o = (size_t)(b * N + n0 + r) * (3 * C) + 2 * C + h * 64 + d;
        sh[d][r] = qh[o]; sl[d][r] = ql[o];
    }
    __syncthreads();
    for (int i = tid; i < 2048; i += 256) {
        int d = i >> 5, c = i & 31;
        size_t o = (size_t)z * D * N + (size_t)d * N + n0 + c;
        vh[o] = sh[d][c]; vl[o] = sl[d][c];
    }
}

// ===========================================================================
// scores_strip: CTA = 128 Q-rows x full 2048 cols of one head.
// Q (128x64 hi/lo, 40KB) staged once, A_hi frags hoisted to registers for the
// whole strip (A_lo re-ldsm'd per tile). K tiles (64 out-cols, 20KB/stage)
// double-buffered in the remaining 40KB. Total smem 81920 -> 2 CTAs/SM.
// Writes raw scaled scores (0.125x) to attn; mask applied later in softmax.
// ===========================================================================
constexpr int SC_QT = 128 * 80;       // 10240: one 128x32 sub-tile (per kc/hl)
constexpr int SC_SB = 4 * SC_QT;      // 40960: B region base
constexpr int SC_BT = 64 * 80;        // 5120: one 64x32 B sub-tile
constexpr int SC_BSTG = 4 * SC_BT;    // 20480: B stage (kc2 x hl2)
constexpr int SC_SMEM = SC_SB + 2 * SC_BSTG;   // 81920

__global__ void __launch_bounds__(256, 2) scores_strip(
    const __nv_bfloat16* __restrict__ Qh, const __nv_bfloat16* __restrict__ Ql,
    float* __restrict__ attn) {
    extern __shared__ char smem[];
    const int tid = threadIdx.x, lane = tid & 31, wid = tid >> 5;
    const int wm = wid & 3, wn = wid >> 2;
    const int z = blockIdx.z, bz = z >> 4, hz = z & 15;
    const int m0 = blockIdx.x * 128;
    const uint32_t sbase = smem_u32(smem);

    auto load_b = [&](int s, int t) {
        #pragma unroll
        for (int kc = 0; kc < 2; kc++) {
            int i = tid;                       // 64 rows x 4 c4 = 256 = blockDim
            int r = i >> 2, c4 = i & 3;
            size_t src = (size_t)(bz * N + t * 64 + r) * (3 * C) + C + hz * 64 + kc * 32 + c4 * 8;
            uint32_t d = sbase + SC_SB + s * SC_BSTG + (kc * 2) * SC_BT + r * 80 + c4 * 16;
            cpasync16(d,         Qh + src);
            cpasync16(d + SC_BT, Ql + src);
        }
        cp_commit();
    };

    // Q load (group 0, committed together with B tile 0)
    #pragma unroll
    for (int kc = 0; kc < 2; kc++) {
        #pragma unroll
        for (int i = tid; i < 512; i += 256) {
            int r = i >> 2, c4 = i & 3;
            size_t src = (size_t)(bz * N + m0 + r) * (3 * C) + hz * 64 + kc * 32 + c4 * 8;
            uint32_t d = sbase + (kc * 2) * SC_QT + r * 80 + c4 * 16;
            cpasync16(d,         Qh + src);
            cpasync16(d + SC_QT, Ql + src);
        }
    }
    load_b(0, 0);      // commit: group0 = Q + B0
    load_b(1, 1);      // group1 = B1
    cp_wait<1>();      // group0 done (Q + B0 ready)
    __syncthreads();

    const int arow = wm * 32 + (lane & 15);
    const int acolb = ((lane >> 4) << 4);
    const int brow = (lane & 7) + ((lane >> 4) << 3);
    const int bcolb = (((lane >> 3) & 1) << 4);

    // hoist A_hi frags for the whole strip (32 regs)
    uint32_t afh[2][2][2][4 / 2 * 2];   // [kc][kk][ma][4]
    #pragma unroll
    for (int kc = 0; kc < 2; kc++)
        #pragma unroll
        for (int kk = 0; kk < 2; kk++)
            #pragma unroll
            for (int ma = 0; ma < 2; ma++)
                ldsm4(afh[kc][kk][ma],
                      sbase + (kc * 2) * SC_QT + (arow + ma * 16) * 80 + kk * 32 + acolb);

    for (int t = 0; t < 32; t++) {
        float acc[2][4][4];
        #pragma unroll
        for (int a = 0; a < 2; a++)
            #pragma unroll
            for (int b2 = 0; b2 < 4; b2++)
                #pragma unroll
                for (int c = 0; c < 4; c++) acc[a][b2][c] = 0.f;

        const uint32_t bst = sbase + SC_SB + (t & 1) * SC_BSTG;
        #pragma unroll
        for (int kc = 0; kc < 2; kc++)
            #pragma unroll
            for (int kk = 0; kk < 2; kk++) {
                uint32_t afl[2][4];
                #pragma unroll
                for (int ma = 0; ma < 2; ma++)
                    ldsm4(afl[ma],
                          sbase + (kc * 2) * SC_QT + SC_QT + (arow + ma * 16) * 80 + kk * 32 + acolb);
                uint32_t bfh[4][2], bfl[4][2];
                #pragma unroll
                for (int p = 0; p < 2; p++) {
                    uint32_t r4[4];
                    uint32_t bd = bst + (kc * 2) * SC_BT + (wn * 32 + p * 16 + brow) * 80 + kk * 32 + bcolb;
                    ldsm4(r4, bd);
                    bfh[2*p][0] = r4[0]; bfh[2*p][1] = r4[1];
                    bfh[2*p+1][0] = r4[2]; bfh[2*p+1][1] = r4[3];
                    ldsm4(r4, bd + SC_BT);
                    bfl[2*p][0] = r4[0]; bfl[2*p][1] = r4[1];
                    bfl[2*p+1][0] = r4[2]; bfl[2*p+1][1] = r4[3];
                }
                #pragma unroll
                for (int ma = 0; ma < 2; ma++)
                    #pragma unroll
                    for (int na = 0; na < 4; na++) {
                        mma16816(acc[ma][na], afh[kc][kk][ma], bfh[na]);
                        mma16816(acc[ma][na], afh[kc][kk][ma], bfl[na]);
                        mma16816(acc[ma][na], afl[ma], bfh[na]);
                    }
            }

        // epilogue: raw scaled scores
        const int ct0 = t * 64;
        #pragma unroll
        for (int ma = 0; ma < 2; ma++)
            #pragma unroll
            for (int na = 0; na < 4; na++) {
                const int gc = ct0 + wn * 32 + na * 8 + ((lane & 3) << 1);
                #pragma unroll
                for (int h2 = 0; h2 < 2; h2++) {
                    const int gr = m0 + wm * 32 + ma * 16 + h2 * 8 + (lane >> 2);
                    *reinterpret_cast<float2*>(attn + (size_t)z * N * N + (size_t)gr * N + gc)
                        = make_float2(acc[ma][na][h2 * 2] * 0.125f,
                                      acc[ma][na][h2 * 2 + 1] * 0.125f);
                }
            }
        __syncthreads();
        if (t + 1 < 32) {
            if (t + 2 < 32) { load_b(t & 1, t + 2); cp_wait<1>(); }
            else cp_wait<0>();
            __syncthreads();
        }
    }
}

// ===========================================================================
// HMMA GEMM (NT), 2-stage cp.async, 80 KB smem, __launch_bounds__(256, 2).
// EPI: 1 = split -> hi/lo   2 = +bias+resid -> fp32   3 = gelu(+bias) -> hi/lo
// ===========================================================================
template<int BN_, int EPI>
__global__ void __launch_bounds__(256, 2) hgemm(
    const __nv_bfloat16* __restrict__ Ah, const __nv_bfloat16* __restrict__ Al,
    int lda, long long sAb, long long sAh,
    const __nv_bfloat16* __restrict__ Bh, const __nv_bfloat16* __restrict__ Bl,
    int ldb, long long sBb, long long sBh,
    float* __restrict__ Cf, __nv_bfloat16* __restrict__ Chi, __nv_bfloat16* __restrict__ Clo,
    int ldc, long long sCb, long long sCh,
    int K, const float* __restrict__ bias, const float* __restrict__ resid) {
    extern __shared__ char smem[];
    constexpr int ROWB = 80;
    constexpr int ATILE = 128 * ROWB;
    constexpr int STAGE = 2 * ATILE + 2 * BN_ * ROWB;
    constexpr int WTN = BN_ / 2;
    constexpr int NA = WTN / 8;

    const int tid = threadIdx.x, lane = tid & 31, wid = tid >> 5;
    const int wm = wid & 3, wn = wid >> 2;
    const int z = blockIdx.z, bz = z >> 4, hz = z & 15;
    Ah += (size_t)bz * sAb + (size_t)hz * sAh;
    Al += (size_t)bz * sAb + (size_t)hz * sAh;
    Bh += (size_t)bz * sBb + (size_t)hz * sBh;
    Bl += (size_t)bz * sBb + (size_t)hz * sBh;
    const size_t coff = (size_t)bz * sCb + (size_t)hz * sCh;
    const int m0 = blockIdx.y * 128, n0 = blockIdx.x * BN_;
    const uint32_t sbase = smem_u32(smem);

    auto load_stage = [&](int s, int k0) {
        const uint32_t st = sbase + s * STAGE;
        #pragma unroll
        for (int i = tid; i < 512; i += 256) {
            int r = i >> 2, c4 = i & 3;
            uint32_t d = st + r * ROWB + c4 * 16;
            cpasync16(d,         Ah + (size_t)(m0 + r) * lda + k0 + c4 * 8);
            cpasync16(d + ATILE, Al + (size_t)(m0 + r) * lda + k0 + c4 * 8);
        }
        #pragma unroll
        for (int i = tid; i < BN_ * 4; i += 256) {
            int r = i >> 2, c4 = i & 3;
            uint32_t d = st + 2 * ATILE + r * ROWB + c4 * 16;
            cpasync16(d,              Bh + (size_t)(n0 + r) * ldb + k0 + c4 * 8);
            cpasync16(d + BN_ * ROWB, Bl + (size_t)(n0 + r) * ldb + k0 + c4 * 8);
        }
        cp_commit();
    };

    float acc[2][NA][4];
    #pragma unroll
    for (int a = 0; a < 2; a++)
        #pragma unroll
        for (int b2 = 0; b2 < NA; b2++)
            #pragma unroll
            for (int c = 0; c < 4; c++) acc[a][b2][c] = 0.f;

    const int nch = K >> 5;
    load_stage(0, 0);
    for (int ch = 0; ch < nch; ch++) {
        if (ch + 1 < nch) { load_stage((ch + 1) & 1, (ch + 1) << 5); cp_wait<1>(); }
        else cp_wait<0>();
        __syncthreads();

        const uint32_t st  = sbase + (ch & 1) * STAGE;
        const uint32_t bst = st + 2 * ATILE;
        const int arow = wm * 32 + (lane & 15);
        const int acolb = ((lane >> 4) << 4);
        const int brow = (lane & 7) + ((lane >> 4) << 3);
        const int bcolb = (((lane >> 3) & 1) << 4);
        #pragma unroll
        for (int ks = 0; ks < 2; ks++) {
            uint32_t afh[2][4], afl[2][4];
            #pragma unroll
            for (int ma = 0; ma < 2; ma++) {
                uint32_t ad = st + (arow + ma * 16) * ROWB + ks * 32 + acolb;
                ldsm4(afh[ma], ad);
                ldsm4(afl[ma], ad + ATILE);
            }
            uint32_t bfh[NA][2], bfl[NA][2];
            #pragma unroll
            for (int p = 0; p < NA / 2; p++) {
                uint32_t r4[4];
                uint32_t bd = bst + (wn * WTN + p * 16 + brow) * ROWB + ks * 32 + bcolb;
                ldsm4(r4, bd);
                bfh[2*p][0] = r4[0]; bfh[2*p][1] = r4[1];
                bfh[2*p+1][0] = r4[2]; bfh[2*p+1][1] = r4[3];
                ldsm4(r4, bd + BN_ * ROWB);
                bfl[2*p][0] = r4[0]; bfl[2*p][1] = r4[1];
                bfl[2*p+1][0] = r4[2]; bfl[2*p+1][1] = r4[3];
            }
            #pragma unroll
            for (int ma = 0; ma < 2; ma++)
                #pragma unroll
                for (int na = 0; na < NA; na++) {
                    mma16816(acc[ma][na], afh[ma], bfh[na]);
                    mma16816(acc[ma][na], afh[ma], bfl[na]);
                    mma16816(acc[ma][na], afl[ma], bfh[na]);
                }
        }
        __syncthreads();
    }

    #pragma unroll
    for (int ma = 0; ma < 2; ma++)
        #pragma unroll
        for (int na = 0; na < NA; na++) {
            const int gr0 = m0 + wm * 32 + ma * 16 + (lane >> 2);
            const int gc  = n0 + wn * WTN + na * 8 + ((lane & 3) << 1);
            #pragma unroll
            for (int h2 = 0; h2 < 2; h2++) {
                const int gr = gr0 + h2 * 8;
                float v0 = acc[ma][na][h2 * 2], v1 = acc[ma][na][h2 * 2 + 1];
                const size_t o = coff + (size_t)gr * ldc + gc;
                if (EPI == 1) split2store(Chi + o, Clo + o, v0, v1);
                if (EPI == 2) {
                    *reinterpret_cast<float2*>(Cf + o) = make_float2(
                        v0 + bias[gc]     + resid[(size_t)gr * ldc + gc],
                        v1 + bias[gc + 1] + resid[(size_t)gr * ldc + gc + 1]);
                }
                if (EPI == 3) {
                    float t0 = gelu_exact(v0 + bias[gc]);
                    float t1 = gelu_exact(v1 + bias[gc + 1]);
                    split2store(Chi + o, Clo + o, t0, t1);
                }
            }
        }
}

// ===========================================================================
// attn @ V: A = fp32 attn [N,N] per head, converted to bf16 hi/lo in regs
// while staging to SMEM. 2-stage, 60 KB smem, __launch_bounds__(256, 2).
// ===========================================================================
__global__ void __launch_bounds__(256, 2) av_gemm(
    const float* __restrict__ attn,
    const __nv_bfloat16* __restrict__ Vh, const __nv_bfloat16* __restrict__ Vl,
    __nv_bfloat16* __restrict__ Ohi, __nv_bfloat16* __restrict__ Olo) {
    extern __shared__ char smem[];
    constexpr int ROWB = 80;
    constexpr int ATILE = 128 * ROWB;             // 10240
    constexpr int BTILE = 64 * ROWB;              // 5120
    constexpr int STAGE = 2 * ATILE + 2 * BTILE;  // 30720
    constexpr int NA = 4;

    const int tid = threadIdx.x, lane = tid & 31, wid = tid >> 5;
    const int wm = wid & 3, wn = wid >> 2;
    const int z = blockIdx.z, bz = z >> 4, hz = z & 15;
    const int m0 = blockIdx.x * 128;
    const float* Ab = attn + (size_t)z * N * N;
    const __nv_bfloat16* Bh = Vh + (size_t)z * D * N;
    const __nv_bfloat16* Bl = Vl + (size_t)z * D * N;
    const uint32_t sbase = smem_u32(smem);

    float4 areg[4];
    auto ldg_A = [&](int k0) {
        #pragma unroll
        for (int j = 0; j < 4; j++) {
            int i = tid + j * 256;
            int r = i >> 3, c4 = i & 7;
            areg[j] = *reinterpret_cast<const float4*>(Ab + (size_t)(m0 + r) * N + k0 + c4 * 4);
        }
    };
    auto sts_A = [&](int s) {
        #pragma unroll
        for (int j = 0; j < 4; j++) {
            int i = tid + j * 256;
            int r = i >> 3, c4 = i & 7;
            uint2 h = cvt_hi2(areg[j]);
            uint2 l = cvt_lo2(areg[j], h);
            *reinterpret_cast<uint2*>(smem + s * STAGE + r * ROWB + c4 * 8) = h;
            *reinterpret_cast<uint2*>(smem + s * STAGE + ATILE + r * ROWB + c4 * 8) = l;
        }
    };
    auto ld_B = [&](int s, int k0) {
        const uint32_t st = sbase + s * STAGE + 2 * ATILE;
        {
            int i = tid;
            int r = i >> 2, c4 = i & 3;
            uint32_t d = st + r * ROWB + c4 * 16;
            cpasync16(d,         Bh + (size_t)r * N + k0 + c4 * 8);
            cpasync16(d + BTILE, Bl + (size_t)r * N + k0 + c4 * 8);
        }
        cp_commit();
    };

    float acc[2][NA][4];
    #pragma unroll
    for (int a = 0; a < 2; a++)
        #pragma unroll
        for (int b2 = 0; b2 < NA; b2++)
            #pragma unroll
            for (int c = 0; c < 4; c++) acc[a][b2][c] = 0.f;

    constexpr int nch = N / 32;    // 64
    ldg_A(0);
    sts_A(0);
    ld_B(0, 0);
    ldg_A(32);                     // regs now hold A(1)

    for (int ch = 0; ch < nch; ch++) {
        if (ch + 1 < nch) {
            sts_A((ch + 1) & 1);
            ld_B((ch + 1) & 1, (ch + 1) << 5);
        }
        if (ch + 2 < nch) ldg_A((ch + 2) << 5);
        if (ch + 1 < nch) cp_wait<1>(); else cp_wait<0>();
        __syncthreads();

        const uint32_t st  = sbase + (ch & 1) * STAGE;
        const uint32_t bst = st + 2 * ATILE;
        const int arow = wm * 32 + (lane & 15);
        const int acolb = ((lane >> 4) << 4);
        const int brow = (lane & 7) + ((lane >> 4) << 3);
        const int bcolb = (((lane >> 3) & 1) << 4);
        #pragma unroll
        for (int ks = 0; ks < 2; ks++) {
            uint32_t afh[2][4], afl[2][4];
            #pragma unroll
            for (int ma = 0; ma < 2; ma++) {
                uint32_t ad = st + (arow + ma * 16) * ROWB + ks * 32 + acolb;
                ldsm4(afh[ma], ad);
                ldsm4(afl[ma], ad + ATILE);
            }
            uint32_t bfh[NA][2], bfl[NA][2];
            #pragma unroll
            for (int p = 0; p < NA / 2; p++) {
                uint32_t r4[4];
                uint32_t bd = bst + (wn * 32 + p * 16 + brow) * ROWB + ks * 32 + bcolb;
                ldsm4(r4, bd);
                bfh[2*p][0] = r4[0]; bfh[2*p][1] = r4[1];
                bfh[2*p+1][0] = r4[2]; bfh[2*p+1][1] = r4[3];
                ldsm4(r4, bd + BTILE);
                bfl[2*p][0] = r4[0]; bfl[2*p][1] = r4[1];
                bfl[2*p+1][0] = r4[2]; bfl[2*p+1][1] = r4[3];
            }
            #pragma unroll
            for (int ma = 0; ma < 2; ma++)
                #pragma unroll
                for (int na = 0; na < NA; na++) {
                    mma16816(acc[ma][na], afh[ma], bfh[na]);
                    mma16816(acc[ma][na], afh[ma], bfl[na]);
                    mma16816(acc[ma][na], afl[ma], bfh[na]);
                }
        }
        __syncthreads();
    }

    #pragma unroll
    for (int ma = 0; ma < 2; ma++)
        #pragma unroll
        for (int na = 0; na < NA; na++) {
            const int lr0 = wm * 32 + ma * 16 + (lane >> 2);
            const int gc  = hz * 64 + wn * 32 + na * 8 + ((lane & 3) << 1);
            #pragma unroll
            for (int h2 = 0; h2 < 2; h2++) {
                const size_t o = (size_t)(bz * N + m0 + lr0 + h2 * 8) * C + gc;
                split2store(Ohi + o, Olo + o, acc[ma][na][h2 * 2], acc[ma][na][h2 * 2 + 1]);
            }
        }
}

constexpr int SMB128 = 2 * (2 * 128 * 80 + 2 * 128 * 80);  // 81920
constexpr int SMB_AV = 2 * (2 * 128 * 80 + 2 * 64 * 80);   // 61440

// ---------------- host ----------------
extern "C" void kernel_launch(void* const* d_in, const int* in_sizes, int n_in,
                              void* d_out, int out_size) {
    const float* x      = (const float*)d_in[0];
    const int*   mask   = (const int*)  d_in[1];
    const float* qkv_w  = (const float*)d_in[2];
    const float* proj_w = (const float*)d_in[3];
    const float* proj_b = (const float*)d_in[4];
    const float* ln1_g  = (const float*)d_in[5];
    const float* ln1_b  = (const float*)d_in[6];
    const float* ln2_g  = (const float*)d_in[7];
    const float* ln2_b  = (const float*)d_in[8];
    const float* fc1_w  = (const float*)d_in[9];
    const float* fc1_b  = (const float*)d_in[10];
    const float* fc2_w  = (const float*)d_in[11];
    const float* fc2_b  = (const float*)d_in[12];
    float* out_x    = (float*)d_out;
    float* out_attn = out_x + (size_t)B * N * C;

    cudaFuncSetAttribute(hgemm<128,1>, cudaFuncAttributeMaxDynamicSharedMemorySize, SMB128);
    cudaFuncSetAttribute(hgemm<128,2>, cudaFuncAttributeMaxDynamicSharedMemorySize, SMB128);
    cudaFuncSetAttribute(hgemm<128,3>, cudaFuncAttributeMaxDynamicSharedMemorySize, SMB128);
    cudaFuncSetAttribute(av_gemm,      cudaFuncAttributeMaxDynamicSharedMemorySize, SMB_AV);
    cudaFuncSetAttribute(scores_strip, cudaFuncAttributeMaxDynamicSharedMemorySize, SC_SMEM);

    __nv_bfloat16 *xnh, *xnl, *qwh, *qwl, *pwh, *pwl, *f1h, *f1l, *f2h, *f2l;
    __nv_bfloat16 *qh, *ql, *vth, *vtl, *aoh, *aol, *hh, *hl;
    float* x1;
    cudaGetSymbolAddress((void**)&xnh, g_xnh); cudaGetSymbolAddress((void**)&xnl, g_xnl);
    cudaGetSymbolAddress((void**)&qwh, g_qwh); cudaGetSymbolAddress((void**)&qwl, g_qwl);
    cudaGetSymbolAddress((void**)&pwh, g_pwh); cudaGetSymbolAddress((void**)&pwl, g_pwl);
    cudaGetSymbolAddress((void**)&f1h, g_f1h); cudaGetSymbolAddress((void**)&f1l, g_f1l);
    cudaGetSymbolAddress((void**)&f2h, g_f2h); cudaGetSymbolAddress((void**)&f2l, g_f2l);
    cudaGetSymbolAddress((void**)&qh,  g_qh);  cudaGetSymbolAddress((void**)&ql,  g_ql);
    cudaGetSymbolAddress((void**)&vth, g_vth); cudaGetSymbolAddress((void**)&vtl, g_vtl);
    cudaGetSymbolAddress((void**)&aoh, g_aoh); cudaGetSymbolAddress((void**)&aol, g_aol);
    cudaGetSymbolAddress((void**)&hh,  g_hh);  cudaGetSymbolAddress((void**)&hl,  g_hl);
    cudaGetSymbolAddress((void**)&x1,  g_x1);

    // weight splits
    split_kernel<<<3 * C * C / 4 / 256, 256>>>(qkv_w, qwh, qwl, 3 * C * C / 4);
    split_kernel<<<C * C / 4 / 256, 256>>>(proj_w, pwh, pwl, C * C / 4);
    split_kernel<<<DFF * C / 4 / 256, 256>>>(fc1_w, f1h, f1l, DFF * C / 4);
    split_kernel<<<C * DFF / 4 / 256, 256>>>(fc2_w, f2h, f2l, C * DFF / 4);

    // 1) ln1 -> xn (hi/lo)
    ln_split<<<BNR, 256>>>(x, ln1_g, ln1_b, xnh, xnl);
    // 2) qkv = xn @ qkv_w^T -> split
    hgemm<128,1><<<dim3(24, 32, 1), 256, SMB128>>>(
        xnh, xnl, C, 0, 0, qwh, qwl, C, 0, 0,
        nullptr, qh, ql, 3 * C, 0, 0, C, nullptr, nullptr);
    // 3) scores = 0.125 * Q @ K^T (strip kernel, Q reused across the row)
    scores_strip<<<dim3(16, 1, 32), 256, SC_SMEM>>>(qh, ql, out_attn);
    // 4) masked softmax (in-place, fp32, float4)
    softmax_kernel<<<B * H * N, 256>>>(out_attn, mask);
    // 5) V transpose (per-head [D, N] hi/lo)
    vtrans<<<dim3(N / 32, 1, B * H), 256>>>(qh, ql, vth, vtl);
    // 6) ao = attn @ V (reads fp32 attn, converts in-kernel) -> split
    av_gemm<<<dim3(16, 1, 32), 256, SMB_AV>>>(out_attn, vth, vtl, aoh, aol);
    // 7) x1 = x + ao @ proj_w^T + proj_b
    hgemm<128,2><<<dim3(8, 32, 1), 256, SMB128>>>(
        aoh, aol, C, 0, 0, pwh, pwl, C, 0, 0,
        x1, nullptr, nullptr, C, 0, 0, C, proj_b, x);
    // 8) ln2 -> xn (hi/lo)
    ln_split<<<BNR, 256>>>(x1, ln2_g, ln2_b, xnh, xnl);
    // 9) h = gelu(xn @ fc1_w^T + fc1_b) -> split
    hgemm<128,3><<<dim3(32, 32, 1), 256, SMB128>>>(
        xnh, xnl, C, 0, 0, f1h, f1l, C, 0, 0,
        nullptr, hh, hl, DFF, 0, 0, C, fc1_b, nullptr);
    // 10) out_x = x1 + h @ fc2_w^T + fc2_b
    hgemm<128,2><<<dim3(8, 32, 1), 256, SMB128>>>(
        hh, hl, DFF, 0, 0, f2h, f2l, DFF, 0, 0,
        out_x, nullptr, nullptr, C, 0, 0, DFF, fc2_b, x1);
}

// round 11
// speedup vs baseline: 1.9569x; 1.0945x over previous
#include <cuda_runtime.h>
#include <cuda_bf16.h>
#include <math.h>
#include <stdint.h>

constexpr int B = 2, N = 2048, C = 1024, H = 16, D = 64, DFF = 4096;
constexpr int BNR = B * N;   // 4096
constexpr float EPS = 1e-5f;

// ---------------- low-level helpers (family-generic PTX: no tcgen05) -------
__device__ __forceinline__ uint32_t smem_u32(const void* p) {
    uint32_t a;
    asm("{ .reg .u64 t; cvta.to.shared.u64 t, %1; cvt.u32.u64 %0, t; }" : "=r"(a) : "l"(p));
    return a;
}
__device__ __forceinline__ void cpasync16(uint32_t dst, const void* src) {
    asm volatile("cp.async.cg.shared.global [%0], [%1], 16;" :: "r"(dst), "l"(src));
}
__device__ __forceinline__ void cp_commit() {
    asm volatile("cp.async.commit_group;");
}
template<int Nw>
__device__ __forceinline__ void cp_wait() {
    asm volatile("cp.async.wait_group %0;" :: "n"(Nw));
}
__device__ __forceinline__ void ldsm4(uint32_t* r, uint32_t addr) {
    asm volatile("ldmatrix.sync.aligned.m8n8.x4.shared.b16 {%0,%1,%2,%3}, [%4];"
        : "=r"(r[0]), "=r"(r[1]), "=r"(r[2]), "=r"(r[3]) : "r"(addr));
}
__device__ __forceinline__ void mma16816(float* d, const uint32_t* a, const uint32_t* b) {
    asm volatile("mma.sync.aligned.m16n8k16.row.col.f32.bf16.bf16.f32 "
        "{%0,%1,%2,%3}, {%4,%5,%6,%7}, {%8,%9}, {%0,%1,%2,%3};"
        : "+f"(d[0]), "+f"(d[1]), "+f"(d[2]), "+f"(d[3])
        : "r"(a[0]), "r"(a[1]), "r"(a[2]), "r"(a[3]), "r"(b[0]), "r"(b[1]));
}
__device__ __forceinline__ float gelu_exact(float v) {
    return 0.5f * v * (1.0f + erff(v * 0.70710678118654752f));
}
__device__ __forceinline__ void split2store(__nv_bfloat16* hi, __nv_bfloat16* lo,
                                            float v0, float v1) {
    __nv_bfloat16 h0 = __float2bfloat16(v0), h1 = __float2bfloat16(v1);
    __nv_bfloat162 hh(h0, h1);
    __nv_bfloat162 ll(__float2bfloat16(v0 - __bfloat162float(h0)),
                      __float2bfloat16(v1 - __bfloat162float(h1)));
    *reinterpret_cast<__nv_bfloat162*>(hi) = hh;
    *reinterpret_cast<__nv_bfloat162*>(lo) = ll;
}
__device__ __forceinline__ uint2 cvt_hi2(float4 v) {
    __nv_bfloat162 a(__float2bfloat16(v.x), __float2bfloat16(v.y));
    __nv_bfloat162 b(__float2bfloat16(v.z), __float2bfloat16(v.w));
    return make_uint2(*(uint32_t*)&a, *(uint32_t*)&b);
}
__device__ __forceinline__ uint2 cvt_lo2(float4 v, uint2 hi) {
    __nv_bfloat162 ha = *(__nv_bfloat162*)&hi.x, hb = *(__nv_bfloat162*)&hi.y;
    __nv_bfloat162 a(__float2bfloat16(v.x - __bfloat162float(ha.x)),
                     __float2bfloat16(v.y - __bfloat162float(ha.y)));
    __nv_bfloat162 b(__float2bfloat16(v.z - __bfloat162float(hb.x)),
                     __float2bfloat16(v.w - __bfloat162float(hb.y)));
    return make_uint2(*(uint32_t*)&a, *(uint32_t*)&b);
}
// 64B-row XOR swizzle: 16B chunk c4 of row r -> conflict-free ldmatrix phases
__device__ __forceinline__ uint32_t sw64(int r, int c4) {
    return (uint32_t)(r * 64 + ((c4 ^ ((r >> 1) & 3)) << 4));
}

// ---------------- scratch ----------------
#define GA __device__ __align__(256)
GA __nv_bfloat16 g_xnh[BNR * C],      g_xnl[BNR * C];
GA __nv_bfloat16 g_qwh[3 * C * C],    g_qwl[3 * C * C];
GA __nv_bfloat16 g_pwh[C * C],        g_pwl[C * C];
GA __nv_bfloat16 g_f1h[DFF * C],      g_f1l[DFF * C];
GA __nv_bfloat16 g_f2h[C * DFF],      g_f2l[C * DFF];
GA __nv_bfloat16 g_qh[BNR * 3 * C],   g_ql[BNR * 3 * C];
GA __nv_bfloat16 g_vth[B * H * D * N], g_vtl[B * H * D * N];
GA __nv_bfloat16 g_aoh[BNR * C],      g_aol[BNR * C];
GA __nv_bfloat16 g_hh[BNR * DFF],     g_hl[BNR * DFF];
GA float g_x1[BNR * C];

// ---------------- fp32 -> (hi,lo) bf16 split ----------------
__global__ void split_kernel(const float* __restrict__ s, __nv_bfloat16* __restrict__ hi,
                             __nv_bfloat16* __restrict__ lo, int n4) {
    int i = blockIdx.x * 256 + threadIdx.x;
    if (i >= n4) return;
    float4 v = reinterpret_cast<const float4*>(s)[i];
    uint2 h = cvt_hi2(v);
    uint2 l = cvt_lo2(v, h);
    reinterpret_cast<uint2*>(hi)[i] = h;
    reinterpret_cast<uint2*>(lo)[i] = l;
}

// ---------------- LayerNorm -> split ----------------
__global__ void ln_split(const float* __restrict__ x, const float* __restrict__ g,
                         const float* __restrict__ b, __nv_bfloat16* __restrict__ hi,
                         __nv_bfloat16* __restrict__ lo) {
    const int row = blockIdx.x, tid = threadIdx.x;
    const float* xr = x + (size_t)row * C;
    __shared__ float sd[C];
    __shared__ float red[256];
    float ls = 0.f;
    for (int i = tid; i < C; i += 256) { float v = xr[i]; sd[i] = v; ls += v; }
    red[tid] = ls; __syncthreads();
    for (int s = 128; s > 0; s >>= 1) { if (tid < s) red[tid] += red[tid + s]; __syncthreads(); }
    const float mu = red[0] * (1.0f / C); __syncthreads();
    float lv = 0.f;
    for (int i = tid; i < C; i += 256) { float d = sd[i] - mu; lv += d * d; }
    red[tid] = lv; __syncthreads();
    for (int s = 128; s > 0; s >>= 1) { if (tid < s) red[tid] += red[tid + s]; __syncthreads(); }
    const float rstd = rsqrtf(red[0] * (1.0f / C) + EPS);
    for (int i = tid; i < C; i += 256) {
        float v = (sd[i] - mu) * rstd * g[i] + b[i];
        __nv_bfloat16 h = __float2bfloat16(v);
        hi[(size_t)row * C + i] = h;
        lo[(size_t)row * C + i] = __float2bfloat16(v - __bfloat162float(h));
    }
}

// ---------------- masked softmax (in-place fp32, float4) ----------------
__global__ void softmax_kernel(float* __restrict__ attn, const int* __restrict__ mask) {
    const long long row = blockIdx.x;
    const int b = (int)(row / ((long long)H * N));
    float4* p4 = reinterpret_cast<float4*>(attn + row * (long long)N);
    const int4* mr4 = reinterpret_cast<const int4*>(mask + (size_t)b * N);
    const int tid = threadIdx.x;
    __shared__ float red[256];
    float4 vals[2];
    float lmax = -INFINITY;
    #pragma unroll
    for (int j = 0; j < 2; j++) {
        int i = tid + j * 256;
        float4 v = p4[i];
        int4 m = mr4[i];
        v.x = m.x ? v.x : -INFINITY;
        v.y = m.y ? v.y : -INFINITY;
        v.z = m.z ? v.z : -INFINITY;
        v.w = m.w ? v.w : -INFINITY;
        vals[j] = v;
        lmax = fmaxf(lmax, fmaxf(fmaxf(v.x, v.y), fmaxf(v.z, v.w)));
    }
    red[tid] = lmax; __syncthreads();
    for (int s = 128; s > 0; s >>= 1) { if (tid < s) red[tid] = fmaxf(red[tid], red[tid + s]); __syncthreads(); }
    const float rm = red[0]; __syncthreads();
    float ls = 0.f;
    #pragma unroll
    for (int j = 0; j < 2; j++) {
        float4 v = vals[j];
        v.x = __expf(v.x - rm); v.y = __expf(v.y - rm);
        v.z = __expf(v.z - rm); v.w = __expf(v.w - rm);
        vals[j] = v;
        ls += (v.x + v.y) + (v.z + v.w);
    }
    red[tid] = ls; __syncthreads();
    for (int s = 128; s > 0; s >>= 1) { if (tid < s) red[tid] += red[tid + s]; __syncthreads(); }
    const float inv = 1.0f / red[0];
    #pragma unroll
    for (int j = 0; j < 2; j++) {
        float4 v = vals[j];
        v.x *= inv; v.y *= inv; v.z *= inv; v.w *= inv;
        p4[tid + j * 256] = v;
    }
}

// ---------------- V transpose: qkv[.,2C+h*64+d] -> vt[b,h,d,n] ----------------
__global__ void vtrans(const __nv_bfloat16* __restrict__ qh, const __nv_bfloat16* __restrict__ ql,
                       __nv_bfloat16* __restrict__ vh, __nv_bfloat16* __restrict__ vl) {
    const int z = blockIdx.z, b = z >> 4, h = z & 15;
    const int n0 = blockIdx.x * 32, tid = threadIdx.x;
    __shared__ __nv_bfloat16 sh[64][33], sl[64][33];
    for (int i = tid; i < 2048; i += 256) {
        int r = i >> 6, d = i & 63;
        size_t o = (size_t)(b * N + n0 + r) * (3 * C) + 2 * C + h * 64 + d;
        sh[d][r] = qh[o]; sl[d][r] = ql[o];
    }
    __syncthreads();
    for (int i = tid; i < 2048; i += 256) {
        int d = i >> 5, c = i & 31;
        size_t o = (size_t)z * D * N + (size_t)d * N + n0 + c;
        vh[o] = sh[d][c]; vl[o] = sl[d][c];
    }
}

// ===========================================================================
// scores_strip: CTA = 128 Q-rows x full 2048 cols of one head (80B rows,
// proven). Writes raw scaled scores; mask applied in softmax.
// ===========================================================================
constexpr int SC_QT = 128 * 80;
constexpr int SC_SB = 4 * SC_QT;
constexpr int SC_BT = 64 * 80;
constexpr int SC_BSTG = 4 * SC_BT;
constexpr int SC_SMEM = SC_SB + 2 * SC_BSTG;   // 81920

__global__ void __launch_bounds__(256, 2) scores_strip(
    const __nv_bfloat16* __restrict__ Qh, const __nv_bfloat16* __restrict__ Ql,
    float* __restrict__ attn) {
    extern __shared__ char smem[];
    const int tid = threadIdx.x, lane = tid & 31, wid = tid >> 5;
    const int wm = wid & 3, wn = wid >> 2;
    const int z = blockIdx.z, bz = z >> 4, hz = z & 15;
    const int m0 = blockIdx.x * 128;
    const uint32_t sbase = smem_u32(smem);

    auto load_b = [&](int s, int t) {
        #pragma unroll
        for (int kc = 0; kc < 2; kc++) {
            int i = tid;
            int r = i >> 2, c4 = i & 3;
            size_t src = (size_t)(bz * N + t * 64 + r) * (3 * C) + C + hz * 64 + kc * 32 + c4 * 8;
            uint32_t d = sbase + SC_SB + s * SC_BSTG + (kc * 2) * SC_BT + r * 80 + c4 * 16;
            cpasync16(d,         Qh + src);
            cpasync16(d + SC_BT, Ql + src);
        }
        cp_commit();
    };

    #pragma unroll
    for (int kc = 0; kc < 2; kc++) {
        #pragma unroll
        for (int i = tid; i < 512; i += 256) {
            int r = i >> 2, c4 = i & 3;
            size_t src = (size_t)(bz * N + m0 + r) * (3 * C) + hz * 64 + kc * 32 + c4 * 8;
            uint32_t d = sbase + (kc * 2) * SC_QT + r * 80 + c4 * 16;
            cpasync16(d,         Qh + src);
            cpasync16(d + SC_QT, Ql + src);
        }
    }
    load_b(0, 0);
    load_b(1, 1);
    cp_wait<1>();
    __syncthreads();

    const int arow = wm * 32 + (lane & 15);
    const int acolb = ((lane >> 4) << 4);
    const int brow = (lane & 7) + ((lane >> 4) << 3);
    const int bcolb = (((lane >> 3) & 1) << 4);

    uint32_t afh[2][2][2][4];
    #pragma unroll
    for (int kc = 0; kc < 2; kc++)
        #pragma unroll
        for (int kk = 0; kk < 2; kk++)
            #pragma unroll
            for (int ma = 0; ma < 2; ma++)
                ldsm4(afh[kc][kk][ma],
                      sbase + (kc * 2) * SC_QT + (arow + ma * 16) * 80 + kk * 32 + acolb);

    for (int t = 0; t < 32; t++) {
        float acc[2][4][4];
        #pragma unroll
        for (int a = 0; a < 2; a++)
            #pragma unroll
            for (int b2 = 0; b2 < 4; b2++)
                #pragma unroll
                for (int c = 0; c < 4; c++) acc[a][b2][c] = 0.f;

        const uint32_t bst = sbase + SC_SB + (t & 1) * SC_BSTG;
        #pragma unroll
        for (int kc = 0; kc < 2; kc++)
            #pragma unroll
            for (int kk = 0; kk < 2; kk++) {
                uint32_t afl[2][4];
                #pragma unroll
                for (int ma = 0; ma < 2; ma++)
                    ldsm4(afl[ma],
                          sbase + (kc * 2) * SC_QT + SC_QT + (arow + ma * 16) * 80 + kk * 32 + acolb);
                uint32_t bfh[4][2], bfl[4][2];
                #pragma unroll
                for (int p = 0; p < 2; p++) {
                    uint32_t r4[4];
                    uint32_t bd = bst + (kc * 2) * SC_BT + (wn * 32 + p * 16 + brow) * 80 + kk * 32 + bcolb;
                    ldsm4(r4, bd);
                    bfh[2*p][0] = r4[0]; bfh[2*p][1] = r4[1];
                    bfh[2*p+1][0] = r4[2]; bfh[2*p+1][1] = r4[3];
                    ldsm4(r4, bd + SC_BT);
                    bfl[2*p][0] = r4[0]; bfl[2*p][1] = r4[1];
                    bfl[2*p+1][0] = r4[2]; bfl[2*p+1][1] = r4[3];
                }
                #pragma unroll
                for (int ma = 0; ma < 2; ma++)
                    #pragma unroll
                    for (int na = 0; na < 4; na++) {
                        mma16816(acc[ma][na], afh[kc][kk][ma], bfh[na]);
                        mma16816(acc[ma][na], afh[kc][kk][ma], bfl[na]);
                        mma16816(acc[ma][na], afl[ma], bfh[na]);
                    }
            }

        const int ct0 = t * 64;
        #pragma unroll
        for (int ma = 0; ma < 2; ma++)
            #pragma unroll
            for (int na = 0; na < 4; na++) {
                const int gc = ct0 + wn * 32 + na * 8 + ((lane & 3) << 1);
                #pragma unroll
                for (int h2 = 0; h2 < 2; h2++) {
                    const int gr = m0 + wm * 32 + ma * 16 + h2 * 8 + (lane >> 2);
                    *reinterpret_cast<float2*>(attn + (size_t)z * N * N + (size_t)gr * N + gc)
                        = make_float2(acc[ma][na][h2 * 2] * 0.125f,
                                      acc[ma][na][h2 * 2 + 1] * 0.125f);
                }
            }
        __syncthreads();
        if (t + 1 < 32) {
            if (t + 2 < 32) { load_b(t & 1, t + 2); cp_wait<1>(); }
            else cp_wait<0>();
            __syncthreads();
        }
    }
}

// ===========================================================================
// HMMA GEMM (NT), 3-stage cp.async ring on 64B swizzled rows.
// Stage = 32768 B, 3 stages = 98304 B -> still 2 CTAs/SM (196KB <= 228KB),
// regs forced <=128 by __launch_bounds__(256, 2).
// EPI: 1 = split -> hi/lo   2 = +bias+resid -> fp32   3 = gelu(+bias) -> hi/lo
// ===========================================================================
template<int BN_, int EPI>
__global__ void __launch_bounds__(256, 2) hgemm(
    const __nv_bfloat16* __restrict__ Ah, const __nv_bfloat16* __restrict__ Al,
    int lda, long long sAb, long long sAh,
    const __nv_bfloat16* __restrict__ Bh, const __nv_bfloat16* __restrict__ Bl,
    int ldb, long long sBb, long long sBh,
    float* __restrict__ Cf, __nv_bfloat16* __restrict__ Chi, __nv_bfloat16* __restrict__ Clo,
    int ldc, long long sCb, long long sCh,
    int K, const float* __restrict__ bias, const float* __restrict__ resid) {
    extern __shared__ char smem[];
    constexpr int ATILE = 128 * 64;                 // 8192
    constexpr int BTILE = BN_ * 64;
    constexpr int STAGE = 2 * ATILE + 2 * BTILE;    // 32768 for BN_=128
    constexpr int WTN = BN_ / 2;
    constexpr int NA = WTN / 8;

    const int tid = threadIdx.x, lane = tid & 31, wid = tid >> 5;
    const int wm = wid & 3, wn = wid >> 2;
    const int z = blockIdx.z, bz = z >> 4, hz = z & 15;
    Ah += (size_t)bz * sAb + (size_t)hz * sAh;
    Al += (size_t)bz * sAb + (size_t)hz * sAh;
    Bh += (size_t)bz * sBb + (size_t)hz * sBh;
    Bl += (size_t)bz * sBb + (size_t)hz * sBh;
    const size_t coff = (size_t)bz * sCb + (size_t)hz * sCh;
    const int m0 = blockIdx.y * 128, n0 = blockIdx.x * BN_;
    const uint32_t sbase = smem_u32(smem);

    auto load_stage = [&](int s, int k0) {
        const uint32_t st = sbase + s * STAGE;
        #pragma unroll
        for (int i = tid; i < 512; i += 256) {
            int r = i >> 2, c4 = i & 3;
            uint32_t d = st + sw64(r, c4);
            cpasync16(d,         Ah + (size_t)(m0 + r) * lda + k0 + c4 * 8);
            cpasync16(d + ATILE, Al + (size_t)(m0 + r) * lda + k0 + c4 * 8);
        }
        #pragma unroll
        for (int i = tid; i < BN_ * 4; i += 256) {
            int r = i >> 2, c4 = i & 3;
            uint32_t d = st + 2 * ATILE + sw64(r, c4);
            cpasync16(d,         Bh + (size_t)(n0 + r) * ldb + k0 + c4 * 8);
            cpasync16(d + BTILE, Bl + (size_t)(n0 + r) * ldb + k0 + c4 * 8);
        }
        cp_commit();
    };

    float acc[2][NA][4];
    #pragma unroll
    for (int a = 0; a < 2; a++)
        #pragma unroll
        for (int b2 = 0; b2 < NA; b2++)
            #pragma unroll
            for (int c = 0; c < 4; c++) acc[a][b2][c] = 0.f;

    const int nch = K >> 5;
    load_stage(0, 0);
    if (nch > 1) load_stage(1, 32);

    int s_rd = 0;
    for (int ch = 0; ch < nch; ch++) {
        if (ch + 2 < nch) {
            int s_wr = s_rd + 2; if (s_wr >= 3) s_wr -= 3;
            load_stage(s_wr, (ch + 2) << 5);
            cp_wait<2>();
        } else if (ch + 1 < nch) {
            cp_wait<1>();
        } else {
            cp_wait<0>();
        }
        __syncthreads();

        const uint32_t st  = sbase + s_rd * STAGE;
        const uint32_t bst = st + 2 * ATILE;
        const int arow = wm * 32 + (lane & 15);
        const int ac   = (lane >> 4);
        const int brow = (lane & 7) + ((lane >> 4) << 3);
        const int bc   = ((lane >> 3) & 1);
        #pragma unroll
        for (int ks = 0; ks < 2; ks++) {
            uint32_t afh[2][4], afl[2][4];
            #pragma unroll
            for (int ma = 0; ma < 2; ma++) {
                uint32_t ad = st + sw64(arow + ma * 16, ks * 2 + ac);
                ldsm4(afh[ma], ad);
                ldsm4(afl[ma], ad + ATILE);
            }
            uint32_t bfh[NA][2], bfl[NA][2];
            #pragma unroll
            for (int p = 0; p < NA / 2; p++) {
                uint32_t r4[4];
                uint32_t bd = bst + sw64(wn * WTN + p * 16 + brow, ks * 2 + bc);
                ldsm4(r4, bd);
                bfh[2*p][0] = r4[0]; bfh[2*p][1] = r4[1];
                bfh[2*p+1][0] = r4[2]; bfh[2*p+1][1] = r4[3];
                ldsm4(r4, bd + BTILE);
                bfl[2*p][0] = r4[0]; bfl[2*p][1] = r4[1];
                bfl[2*p+1][0] = r4[2]; bfl[2*p+1][1] = r4[3];
            }
            #pragma unroll
            for (int ma = 0; ma < 2; ma++)
                #pragma unroll
                for (int na = 0; na < NA; na++) {
                    mma16816(acc[ma][na], afh[ma], bfh[na]);
                    mma16816(acc[ma][na], afh[ma], bfl[na]);
                    mma16816(acc[ma][na], afl[ma], bfh[na]);
                }
        }
        __syncthreads();
        s_rd++; if (s_rd == 3) s_rd = 0;
    }

    #pragma unroll
    for (int ma = 0; ma < 2; ma++)
        #pragma unroll
        for (int na = 0; na < NA; na++) {
            const int gr0 = m0 + wm * 32 + ma * 16 + (lane >> 2);
            const int gc  = n0 + wn * WTN + na * 8 + ((lane & 3) << 1);
            #pragma unroll
            for (int h2 = 0; h2 < 2; h2++) {
                const int gr = gr0 + h2 * 8;
                float v0 = acc[ma][na][h2 * 2], v1 = acc[ma][na][h2 * 2 + 1];
                const size_t o = coff + (size_t)gr * ldc + gc;
                if (EPI == 1) split2store(Chi + o, Clo + o, v0, v1);
                if (EPI == 2) {
                    *reinterpret_cast<float2*>(Cf + o) = make_float2(
                        v0 + bias[gc]     + resid[(size_t)gr * ldc + gc],
                        v1 + bias[gc + 1] + resid[(size_t)gr * ldc + gc + 1]);
                }
                if (EPI == 3) {
                    float t0 = gelu_exact(v0 + bias[gc]);
                    float t1 = gelu_exact(v1 + bias[gc + 1]);
                    split2store(Chi + o, Clo + o, t0, t1);
                }
            }
        }
}

// ===========================================================================
// attn @ V (80B rows, proven): fp32 attn converted in regs, 2-stage.
// ===========================================================================
__global__ void __launch_bounds__(256, 2) av_gemm(
    const float* __restrict__ attn,
    const __nv_bfloat16* __restrict__ Vh, const __nv_bfloat16* __restrict__ Vl,
    __nv_bfloat16* __restrict__ Ohi, __nv_bfloat16* __restrict__ Olo) {
    extern __shared__ char smem[];
    constexpr int ROWB = 80;
    constexpr int ATILE = 128 * ROWB;
    constexpr int BTILE = 64 * ROWB;
    constexpr int STAGE = 2 * ATILE + 2 * BTILE;
    constexpr int NA = 4;

    const int tid = threadIdx.x, lane = tid & 31, wid = tid >> 5;
    const int wm = wid & 3, wn = wid >> 2;
    const int z = blockIdx.z, bz = z >> 4, hz = z & 15;
    const int m0 = blockIdx.x * 128;
    const float* Ab = attn + (size_t)z * N * N;
    const __nv_bfloat16* Bh = Vh + (size_t)z * D * N;
    const __nv_bfloat16* Bl = Vl + (size_t)z * D * N;
    const uint32_t sbase = smem_u32(smem);

    float4 areg[4];
    auto ldg_A = [&](int k0) {
        #pragma unroll
        for (int j = 0; j < 4; j++) {
            int i = tid + j * 256;
            int r = i >> 3, c4 = i & 7;
            areg[j] = *reinterpret_cast<const float4*>(Ab + (size_t)(m0 + r) * N + k0 + c4 * 4);
        }
    };
    auto sts_A = [&](int s) {
        #pragma unroll
        for (int j = 0; j < 4; j++) {
            int i = tid + j * 256;
            int r = i >> 3, c4 = i & 7;
            uint2 h = cvt_hi2(areg[j]);
            uint2 l = cvt_lo2(areg[j], h);
            *reinterpret_cast<uint2*>(smem + s * STAGE + r * ROWB + c4 * 8) = h;
            *reinterpret_cast<uint2*>(smem + s * STAGE + ATILE + r * ROWB + c4 * 8) = l;
        }
    };
    auto ld_B = [&](int s, int k0) {
        const uint32_t st = sbase + s * STAGE + 2 * ATILE;
        {
            int i = tid;
            int r = i >> 2, c4 = i & 3;
            uint32_t d = st + r * ROWB + c4 * 16;
            cpasync16(d,         Bh + (size_t)r * N + k0 + c4 * 8);
            cpasync16(d + BTILE, Bl + (size_t)r * N + k0 + c4 * 8);
        }
        cp_commit();
    };

    float acc[2][NA][4];
    #pragma unroll
    for (int a = 0; a < 2; a++)
        #pragma unroll
        for (int b2 = 0; b2 < NA; b2++)
            #pragma unroll
            for (int c = 0; c < 4; c++) acc[a][b2][c] = 0.f;

    constexpr int nch = N / 32;
    ldg_A(0);
    sts_A(0);
    ld_B(0, 0);
    ldg_A(32);

    for (int ch = 0; ch < nch; ch++) {
        if (ch + 1 < nch) {
            sts_A((ch + 1) & 1);
            ld_B((ch + 1) & 1, (ch + 1) << 5);
        }
        if (ch + 2 < nch) ldg_A((ch + 2) << 5);
        if (ch + 1 < nch) cp_wait<1>(); else cp_wait<0>();
        __syncthreads();

        const uint32_t st  = sbase + (ch & 1) * STAGE;
        const uint32_t bst = st + 2 * ATILE;
        const int arow = wm * 32 + (lane & 15);
        const int acolb = ((lane >> 4) << 4);
        const int brow = (lane & 7) + ((lane >> 4) << 3);
        const int bcolb = (((lane >> 3) & 1) << 4);
        #pragma unroll
        for (int ks = 0; ks < 2; ks++) {
            uint32_t afh[2][4], afl[2][4];
            #pragma unroll
            for (int ma = 0; ma < 2; ma++) {
                uint32_t ad = st + (arow + ma * 16) * ROWB + ks * 32 + acolb;
                ldsm4(afh[ma], ad);
                ldsm4(afl[ma], ad + ATILE);
            }
            uint32_t bfh[NA][2], bfl[NA][2];
            #pragma unroll
            for (int p = 0; p < NA / 2; p++) {
                uint32_t r4[4];
                uint32_t bd = bst + (wn * 32 + p * 16 + brow) * ROWB + ks * 32 + bcolb;
                ldsm4(r4, bd);
                bfh[2*p][0] = r4[0]; bfh[2*p][1] = r4[1];
                bfh[2*p+1][0] = r4[2]; bfh[2*p+1][1] = r4[3];
                ldsm4(r4, bd + BTILE);
                bfl[2*p][0] = r4[0]; bfl[2*p][1] = r4[1];
                bfl[2*p+1][0] = r4[2]; bfl[2*p+1][1] = r4[3];
            }
            #pragma unroll
            for (int ma = 0; ma < 2; ma++)
                #pragma unroll
                for (int na = 0; na < NA; na++) {
                    mma16816(acc[ma][na], afh[ma], bfh[na]);
                    mma16816(acc[ma][na], afh[ma], bfl[na]);
                    mma16816(acc[ma][na], afl[ma], bfh[na]);
                }
        }
        __syncthreads();
    }

    #pragma unroll
    for (int ma = 0; ma < 2; ma++)
        #pragma unroll
        for (int na = 0; na < NA; na++) {
            const int lr0 = wm * 32 + ma * 16 + (lane >> 2);
            const int gc  = hz * 64 + wn * 32 + na * 8 + ((lane & 3) << 1);
            #pragma unroll
            for (int h2 = 0; h2 < 2; h2++) {
                const size_t o = (size_t)(bz * N + m0 + lr0 + h2 * 8) * C + gc;
                split2store(Ohi + o, Olo + o, acc[ma][na][h2 * 2], acc[ma][na][h2 * 2 + 1]);
            }
        }
}

constexpr int SMB128 = 3 * 32768;                          // 98304 -> 2 CTAs/SM
constexpr int SMB_AV = 2 * (2 * 128 * 80 + 2 * 64 * 80);   // 61440

// ---------------- host ----------------
extern "C" void kernel_launch(void* const* d_in, const int* in_sizes, int n_in,
                              void* d_out, int out_size) {
    const float* x      = (const float*)d_in[0];
    const int*   mask   = (const int*)  d_in[1];
    const float* qkv_w  = (const float*)d_in[2];
    const float* proj_w = (const float*)d_in[3];
    const float* proj_b = (const float*)d_in[4];
    const float* ln1_g  = (const float*)d_in[5];
    const float* ln1_b  = (const float*)d_in[6];
    const float* ln2_g  = (const float*)d_in[7];
    const float* ln2_b  = (const float*)d_in[8];
    const float* fc1_w  = (const float*)d_in[9];
    const float* fc1_b  = (const float*)d_in[10];
    const float* fc2_w  = (const float*)d_in[11];
    const float* fc2_b  = (const float*)d_in[12];
    float* out_x    = (float*)d_out;
    float* out_attn = out_x + (size_t)B * N * C;

    cudaFuncSetAttribute(hgemm<128,1>, cudaFuncAttributeMaxDynamicSharedMemorySize, SMB128);
    cudaFuncSetAttribute(hgemm<128,2>, cudaFuncAttributeMaxDynamicSharedMemorySize, SMB128);
    cudaFuncSetAttribute(hgemm<128,3>, cudaFuncAttributeMaxDynamicSharedMemorySize, SMB128);
    cudaFuncSetAttribute(av_gemm,      cudaFuncAttributeMaxDynamicSharedMemorySize, SMB_AV);
    cudaFuncSetAttribute(scores_strip, cudaFuncAttributeMaxDynamicSharedMemorySize, SC_SMEM);

    __nv_bfloat16 *xnh, *xnl, *qwh, *qwl, *pwh, *pwl, *f1h, *f1l, *f2h, *f2l;
    __nv_bfloat16 *qh, *ql, *vth, *vtl, *aoh, *aol, *hh, *hl;
    float* x1;
    cudaGetSymbolAddress((void**)&xnh, g_xnh); cudaGetSymbolAddress((void**)&xnl, g_xnl);
    cudaGetSymbolAddress((void**)&qwh, g_qwh); cudaGetSymbolAddress((void**)&qwl, g_qwl);
    cudaGetSymbolAddress((void**)&pwh, g_pwh); cudaGetSymbolAddress((void**)&pwl, g_pwl);
    cudaGetSymbolAddress((void**)&f1h, g_f1h); cudaGetSymbolAddress((void**)&f1l, g_f1l);
    cudaGetSymbolAddress((void**)&f2h, g_f2h); cudaGetSymbolAddress((void**)&f2l, g_f2l);
    cudaGetSymbolAddress((void**)&qh,  g_qh);  cudaGetSymbolAddress((void**)&ql,  g_ql);
    cudaGetSymbolAddress((void**)&vth, g_vth); cudaGetSymbolAddress((void**)&vtl, g_vtl);
    cudaGetSymbolAddress((void**)&aoh, g_aoh); cudaGetSymbolAddress((void**)&aol, g_aol);
    cudaGetSymbolAddress((void**)&hh,  g_hh);  cudaGetSymbolAddress((void**)&hl,  g_hl);
    cudaGetSymbolAddress((void**)&x1,  g_x1);

    // weight splits
    split_kernel<<<3 * C * C / 4 / 256, 256>>>(qkv_w, qwh, qwl, 3 * C * C / 4);
    split_kernel<<<C * C / 4 / 256, 256>>>(proj_w, pwh, pwl, C * C / 4);
    split_kernel<<<DFF * C / 4 / 256, 256>>>(fc1_w, f1h, f1l, DFF * C / 4);
    split_kernel<<<C * DFF / 4 / 256, 256>>>(fc2_w, f2h, f2l, C * DFF / 4);

    // 1) ln1 -> xn (hi/lo)
    ln_split<<<BNR, 256>>>(x, ln1_g, ln1_b, xnh, xnl);
    // 2) qkv = xn @ qkv_w^T -> split
    hgemm<128,1><<<dim3(24, 32, 1), 256, SMB128>>>(
        xnh, xnl, C, 0, 0, qwh, qwl, C, 0, 0,
        nullptr, qh, ql, 3 * C, 0, 0, C, nullptr, nullptr);
    // 3) scores = 0.125 * Q @ K^T (strip kernel)
    scores_strip<<<dim3(16, 1, 32), 256, SC_SMEM>>>(qh, ql, out_attn);
    // 4) masked softmax (in-place, fp32, float4)
    softmax_kernel<<<B * H * N, 256>>>(out_attn, mask);
    // 5) V transpose (per-head [D, N] hi/lo)
    vtrans<<<dim3(N / 32, 1, B * H), 256>>>(qh, ql, vth, vtl);
    // 6) ao = attn @ V -> split
    av_gemm<<<dim3(16, 1, 32), 256, SMB_AV>>>(out_attn, vth, vtl, aoh, aol);
    // 7) x1 = x + ao @ proj_w^T + proj_b
    hgemm<128,2><<<dim3(8, 32, 1), 256, SMB128>>>(
        aoh, aol, C, 0, 0, pwh, pwl, C, 0, 0,
        x1, nullptr, nullptr, C, 0, 0, C, proj_b, x);
    // 8) ln2 -> xn (hi/lo)
    ln_split<<<BNR, 256>>>(x1, ln2_g, ln2_b, xnh, xnl);
    // 9) h = gelu(xn @ fc1_w^T + fc1_b) -> split
    hgemm<128,3><<<dim3(32, 32, 1), 256, SMB128>>>(
        xnh, xnl, C, 0, 0, f1h, f1l, C, 0, 0,
        nullptr, hh, hl, DFF, 0, 0, C, fc1_b, nullptr);
    // 10) out_x = x1 + h @ fc2_w^T + fc2_b
    hgemm<128,2><<<dim3(8, 32, 1), 256, SMB128>>>(
        hh, hl, DFF, 0, 0, f2h, f2l, DFF, 0, 0,
        out_x, nullptr, nullptr, C, 0, 0, DFF, fc2_b, x1);
}